// round 9
// baseline (speedup 1.0000x reference)
#include <cuda_runtime.h>
#include <cuda_fp16.h>
#include <cstdint>

#define H 256
#define NGRAPH 128
#define MAXN   20224
#define MAXEG  200192
#define MAXELG 400128

// ---------------- scratch ----------------
__device__ float g_AB[(size_t)MAXN * 512];
__device__ float g_h[(size_t)MAXEG * H];
__device__ float g_nbg[(size_t)MAXEG * 4];
__device__ float g_ebg[(size_t)MAXELG * 4];
__device__ float g_nodeemb[(size_t)MAXN * H];
__device__ double g_bnacc[2 * H];
__device__ float g_bnscale[H];
__device__ float g_bnshift[H];
__device__ float g_gsum[NGRAPH * H];
__device__ float g_cnt[NGRAPH];

// CSR scratch
__device__ int g_deg[MAXEG];
__device__ int g_cursor[MAXEG];
__device__ int g_blk[1024];
__device__ int g_rowptr_lg[MAXEG + 1];
__device__ int g_eidx_lg[MAXELG];
__device__ int g_rowptr_g[MAXN + 1];
__device__ int g_eidx_g[MAXEG];

// int8 activation buffers (pad rows never written -> stay zero)
__device__ char g_node1[(size_t)MAXN * H];
__device__ char g_node0[(size_t)MAXN * H];
__device__ float g_sa_node[MAXN];
__device__ char g_act1[(size_t)MAXEG * H];
__device__ char g_act0[(size_t)MAXEG * H];
__device__ float g_sa_act[MAXEG];

// fp16 hidden + its int8 digits (GEMM2 input)
__device__ __half g_hid[(size_t)MAXEG * 2 * H];
__device__ char g_hq1[(size_t)MAXEG * 2 * H];
__device__ char g_hq0[(size_t)MAXEG * 2 * H];
__device__ float g_sa_hid[MAXEG];
__device__ int g_rowmax[MAXEG];

// int8 weights: slot 0 = msg (512x256), 1..4 = W1 (512 rows x K256), 5..8 = W2 (256 rows x K512)
__device__ char g_wq1[9 * 131072];
__device__ char g_wq0[9 * 131072];
__device__ float g_sbw[9 * 512];

// ======================= helpers =======================
__device__ __forceinline__ uint32_t smem_u32(const void* p) {
    uint32_t a;
    asm("{ .reg .u64 t; cvta.to.shared.u64 t, %1; cvt.u32.u64 %0, t; }" : "=r"(a) : "l"(p));
    return a;
}
#define CP16(dst, src) \
    asm volatile("cp.async.cg.shared.global [%0], [%1], 16;" :: "r"(dst), "l"(src) : "memory")
#define CP_COMMIT() asm volatile("cp.async.commit_group;" ::: "memory")
#define CP_WAIT1()  asm volatile("cp.async.wait_group 1;" ::: "memory")
#define CP_WAIT0()  asm volatile("cp.async.wait_group 0;" ::: "memory")

__device__ __forceinline__ void ldm4(uint32_t (&r)[4], uint32_t addr) {
    asm volatile("ldmatrix.sync.aligned.m8n8.x4.shared.b16 {%0,%1,%2,%3}, [%4];"
                 : "=r"(r[0]), "=r"(r[1]), "=r"(r[2]), "=r"(r[3]) : "r"(addr));
}
__device__ __forceinline__ void mma_s8(int (&d)[4], const uint32_t (&a)[4], const uint32_t* b) {
    asm volatile(
        "mma.sync.aligned.m16n8k32.row.col.s32.s8.s8.s32 "
        "{%0,%1,%2,%3}, {%4,%5,%6,%7}, {%8,%9}, {%0,%1,%2,%3};"
        : "+r"(d[0]), "+r"(d[1]), "+r"(d[2]), "+r"(d[3])
        : "r"(a[0]), "r"(a[1]), "r"(a[2]), "r"(a[3]), "r"(b[0]), "r"(b[1]));
}

// quantize: v -> (q1, q0) digits given inv = 127/rowmax
__device__ __forceinline__ void quant2(float v, float inv, char& d1, char& d0) {
    float q = v * inv;
    int a1 = __float2int_rn(q);
    float rem = (q - (float)a1) * 256.f;
    int a0 = __float2int_rn(rem);
    a0 = max(-127, min(127, a0));
    d1 = (char)a1;
    d0 = (char)a0;
}

// ======================= CSR build kernels =======================
__global__ void zero_int_kernel(int* a, int n)
{
    int i = blockIdx.x * 256 + threadIdx.x;
    if (i < n) a[i] = 0;
}
__global__ void hist_kernel(const int* __restrict__ dst, int* __restrict__ deg, int E)
{
    int i = blockIdx.x * 256 + threadIdx.x;
    if (i < E) atomicAdd(&deg[dst[i]], 1);
}
__global__ void scan_block_sums(const int* __restrict__ deg, int* __restrict__ blk, int n)
{
    __shared__ int sd[256];
    int t = threadIdx.x;
    int i = blockIdx.x * 256 + t;
    sd[t] = (i < n) ? deg[i] : 0;
    __syncthreads();
    for (int o = 128; o > 0; o >>= 1) {
        if (t < o) sd[t] += sd[t + o];
        __syncthreads();
    }
    if (t == 0) blk[blockIdx.x] = sd[0];
}
__global__ void scan_single_block(int* blk, int nb)
{
    __shared__ int tmp[1024];
    int t = threadIdx.x;
    int v = (t < nb) ? blk[t] : 0;
    tmp[t] = v;
    __syncthreads();
    for (int o = 1; o < 1024; o <<= 1) {
        int u = (t >= o) ? tmp[t - o] : 0;
        __syncthreads();
        tmp[t] += u;
        __syncthreads();
    }
    if (t < nb) blk[t] = tmp[t] - v;
}
__global__ void scan_final(const int* __restrict__ deg, const int* __restrict__ blk,
                           int* __restrict__ rowptr, int* __restrict__ cursor, int n, int E)
{
    __shared__ int tmp[256];
    int t = threadIdx.x;
    int i = blockIdx.x * 256 + t;
    int v = (i < n) ? deg[i] : 0;
    tmp[t] = v;
    __syncthreads();
    for (int o = 1; o < 256; o <<= 1) {
        int u = (t >= o) ? tmp[t - o] : 0;
        __syncthreads();
        tmp[t] += u;
        __syncthreads();
    }
    int excl = tmp[t] - v + blk[blockIdx.x];
    if (i < n) { rowptr[i] = excl; cursor[i] = excl; }
    if (blockIdx.x == 0 && t == 0) rowptr[n] = E;
}
__global__ void fill_csr_kernel(const int* __restrict__ dst, int* __restrict__ cursor,
                                int* __restrict__ eidx, int E)
{
    int e = blockIdx.x * 256 + threadIdx.x;
    if (e < E) {
        int p = atomicAdd(&cursor[dst[e]], 1);
        eidx[p] = e;
    }
}

// ======================= int8 2-digit GEMM (all GEMMs) =======================
// C = sa_i*sb_j*(A1B1 + (A1B0 + A0B1)/256). CTA 128x128, 512 thr, 16 warps 32x32,
// BK=32, 3 stages. flags: 1=bias, 2=relu, 4=residual fp32, 8=fp16 out, 16=rowmax
#define RBI 48
#define IA1 0
#define IA0 (128 * RBI)
#define IB1 (2 * 128 * RBI)
#define IB0 (3 * 128 * RBI)
#define ISTG (4 * 128 * RBI)        // 24576
#define I8_SMEM (3 * ISTG)          // 73728

__device__ __forceinline__ void load_stage_i8(uint32_t sbase,
    const char* __restrict__ A1, const char* __restrict__ A0,
    const char* __restrict__ B1, const char* __restrict__ B0,
    int K, int m0, int n0, int k0, int tid)
{
    int t = tid & 255;
    int row = t >> 1, ch = t & 1;
    uint32_t so = (uint32_t)row * RBI + (uint32_t)ch * 16;
    if (tid < 256) {
        size_t ao = (size_t)(m0 + row) * K + k0 + ch * 16;
        CP16(sbase + IA1 + so, A1 + ao);
        CP16(sbase + IA0 + so, A0 + ao);
    } else {
        size_t bo = (size_t)(n0 + row) * K + k0 + ch * 16;
        CP16(sbase + IB1 + so, B1 + bo);
        CP16(sbase + IB0 + so, B0 + bo);
    }
}

__global__ __launch_bounds__(512, 1) void i8_gemm_kernel(
    const char* __restrict__ A1, const char* __restrict__ A0, const float* __restrict__ sa,
    const char* __restrict__ B1, const char* __restrict__ B0, const float* __restrict__ sb,
    const float* __restrict__ bias, const float* __restrict__ res,
    float* __restrict__ Cf, __half* __restrict__ Ch, int* __restrict__ rowmax,
    int M, int N, int K, int flags)
{
    extern __shared__ __align__(128) char smem[];
    uint32_t sbm = smem_u32(smem);
    int tid = threadIdx.x;
    int wid = tid >> 5, lane = tid & 31;
    int m0 = blockIdx.y * 128, n0 = blockIdx.x * 128;   // n fast -> A-tile L2 reuse
    int nk = K >> 5;

    load_stage_i8(sbm, A1, A0, B1, B0, K, m0, n0, 0, tid);
    CP_COMMIT();
    load_stage_i8(sbm + ISTG, A1, A0, B1, B0, K, m0, n0, 32, tid);
    CP_COMMIT();

    int accH[2][4][4], accL[2][4][4];
#pragma unroll
    for (int i = 0; i < 2; i++)
#pragma unroll
        for (int j = 0; j < 4; j++)
#pragma unroll
            for (int q = 0; q < 4; q++) { accH[i][j][q] = 0; accL[i][j][q] = 0; }

    int mo = (wid & 3) * 32, no = (wid >> 2) * 32;
    int a_row = mo + (lane & 15);
    int a16   = lane >> 4;
    int b_row = ((lane >> 4) << 3) + (lane & 7);
    int b16   = (lane >> 3) & 1;

    for (int k = 0; k < nk; k++) {
        if (k == nk - 1) { CP_WAIT0(); } else { CP_WAIT1(); }
        __syncthreads();
        uint32_t base = sbm + (uint32_t)(k % 3) * ISTG;
        if (k + 2 < nk)
            load_stage_i8(sbm + (uint32_t)((k + 2) % 3) * ISTG, A1, A0, B1, B0,
                          K, m0, n0, (k + 2) * 32, tid);
        CP_COMMIT();

        uint32_t a1f[2][4], a0f[2][4], b1f[2][4], b0f[2][4];
#pragma unroll
        for (int i = 0; i < 2; i++) {
            uint32_t aaddr = base + IA1 + (uint32_t)(a_row + i * 16) * RBI + (uint32_t)a16 * 16;
            ldm4(a1f[i], aaddr);
            ldm4(a0f[i], aaddr + (IA0 - IA1));
        }
#pragma unroll
        for (int j = 0; j < 2; j++) {
            uint32_t baddr = base + IB1 + (uint32_t)(no + j * 16 + b_row) * RBI + (uint32_t)b16 * 16;
            ldm4(b1f[j], baddr);
            ldm4(b0f[j], baddr + (IB0 - IB1));
        }
#pragma unroll
        for (int i = 0; i < 2; i++)
#pragma unroll
            for (int j = 0; j < 2; j++)
#pragma unroll
                for (int hh = 0; hh < 2; hh++) {
                    int jb = j * 2 + hh;
                    mma_s8(accH[i][jb], a1f[i], &b1f[j][hh * 2]);
                    mma_s8(accL[i][jb], a1f[i], &b0f[j][hh * 2]);
                    mma_s8(accL[i][jb], a0f[i], &b1f[j][hh * 2]);
                }
    }

    // epilogue
#pragma unroll
    for (int i = 0; i < 2; i++) {
        int r0 = m0 + mo + i * 16 + (lane >> 2);
#pragma unroll
        for (int half = 0; half < 2; half++) {
            int r = r0 + half * 8;
            if (r >= M) continue;
            float sar = sa[r];
            float rmx = 0.f;
#pragma unroll
            for (int jb = 0; jb < 4; jb++) {
                int col = n0 + no + jb * 8 + 2 * (lane & 3);
                float s0 = sar * sb[col], s1 = sar * sb[col + 1];
                float v0 = s0 * ((float)accH[i][jb][half * 2 + 0]
                                 + (float)accL[i][jb][half * 2 + 0] * (1.f / 256.f));
                float v1 = s1 * ((float)accH[i][jb][half * 2 + 1]
                                 + (float)accL[i][jb][half * 2 + 1] * (1.f / 256.f));
                if (flags & 1) { v0 += bias[col]; v1 += bias[col + 1]; }
                if (flags & 4) {
                    float2 t = *(const float2*)(res + (size_t)r * N + col);
                    v0 += t.x; v1 += t.y;
                }
                if (flags & 2) { v0 = fmaxf(v0, 0.f); v1 = fmaxf(v1, 0.f); }
                if (flags & 16) rmx = fmaxf(rmx, fmaxf(v0, v1));
                if (flags & 8) {
                    *(__half2*)(Ch + (size_t)r * N + col) =
                        __halves2half2(__float2half(v0), __float2half(v1));
                } else {
                    *(float2*)(Cf + (size_t)r * N + col) = make_float2(v0, v1);
                }
            }
            if (flags & 16) {
                // lanes 4q..4q+3 share row r; reduce then one atomic (values >= 0)
                rmx = fmaxf(rmx, __shfl_xor_sync(0xffffffffu, rmx, 1));
                rmx = fmaxf(rmx, __shfl_xor_sync(0xffffffffu, rmx, 2));
                if ((lane & 3) == 0) atomicMax(&rowmax[r], __float_as_int(rmx));
            }
        }
    }
}

// ---------------- hid quantizer: fp16 hid -> 2-digit int8 ----------------------
__global__ void hquant_kernel(const __half* __restrict__ hid, const int* __restrict__ rowmax,
                              char* __restrict__ q1, char* __restrict__ q0,
                              float* __restrict__ sav, int NCOL)
{
    int r = blockIdx.x, c = threadIdx.x;
    float rmx = __int_as_float(rowmax[r]);
    float inv = (rmx > 0.f) ? 127.f / rmx : 0.f;
    for (int cc = c; cc < NCOL; cc += 256) {
        float v = __half2float(hid[(size_t)r * NCOL + cc]);
        char d1, d0;
        quant2(v, inv, d1, d0);
        q1[(size_t)r * NCOL + cc] = d1;
        q0[(size_t)r * NCOL + cc] = d0;
    }
    if (c == 0) sav[r] = rmx * (1.f / 127.f);
}

// ---------------- weight int8 quantize: W[K,N] -> digits [N,K] ------------------
__global__ void wquant_kernel(const float* __restrict__ W,
                              char* __restrict__ b1, char* __restrict__ b0,
                              float* __restrict__ sbv, int K, int N)
{
    __shared__ float sred[8];
    int n = blockIdx.x, tid = threadIdx.x;
    int lane = tid & 31, wq = tid >> 5;
    float mx = 0.f;
    for (int k = tid; k < K; k += 256) mx = fmaxf(mx, fabsf(W[(size_t)k * N + n]));
#pragma unroll
    for (int o = 16; o > 0; o >>= 1) mx = fmaxf(mx, __shfl_xor_sync(0xffffffffu, mx, o));
    if (lane == 0) sred[wq] = mx;
    __syncthreads();
    if (tid == 0) {
        float m = 0.f;
#pragma unroll
        for (int i = 0; i < 8; i++) m = fmaxf(m, sred[i]);
        sred[0] = m;
    }
    __syncthreads();
    float wmax = sred[0];
    float inv = (wmax > 0.f) ? 127.f / wmax : 0.f;
    for (int k = tid; k < K; k += 256) {
        char d1, d0;
        quant2(W[(size_t)k * N + n], inv, d1, d0);
        b1[(size_t)n * K + k] = d1;
        b0[(size_t)n * K + k] = d0;
    }
    if (tid == 0) sbv[n] = wmax * (1.f / 127.f);
}

// ---------------- node encoder (int8 out, block = row) --------------------------
__global__ void enc_kernel(const float* __restrict__ xg, const float* __restrict__ W,
                           const float* __restrict__ b,
                           char* __restrict__ o1, char* __restrict__ o0,
                           float* __restrict__ sav)
{
    __shared__ float sx[16];
    __shared__ float sred[8];
    int n = blockIdx.x, c = threadIdx.x;
    int lane = c & 31, wq = c >> 5;
    if (c < 16) sx[c] = xg[(size_t)n * 16 + c];
    __syncthreads();
    float v = b[c];
#pragma unroll
    for (int k = 0; k < 16; k++) v = fmaf(sx[k], W[k * H + c], v);
    float mx = fabsf(v);
#pragma unroll
    for (int o = 16; o > 0; o >>= 1) mx = fmaxf(mx, __shfl_xor_sync(0xffffffffu, mx, o));
    if (lane == 0) sred[wq] = mx;
    __syncthreads();
    if (c == 0) {
        float m = 0.f;
#pragma unroll
        for (int i = 0; i < 8; i++) m = fmaxf(m, sred[i]);
        sred[0] = m;
    }
    __syncthreads();
    float rmax = sred[0];
    float inv = (rmax > 0.f) ? 127.f / rmax : 0.f;
    char d1, d0;
    quant2(v, inv, d1, d0);
    o1[(size_t)n * H + c] = d1;
    o0[(size_t)n * H + c] = d0;
    if (c == 0) sav[n] = rmax * (1.f / 127.f);
}

// ---------------- tiny [E,4]@[4,4]+b projection --------------------------------
__global__ void basis4_kernel(const float* __restrict__ in, const float* __restrict__ W,
                              const float* __restrict__ b, float* __restrict__ out, int E)
{
    int e = blockIdx.x * blockDim.x + threadIdx.x;
    if (e >= E) return;
    float4 x = *(const float4*)(in + (size_t)e * 4);
    float o0 = b[0] + x.x * W[0] + x.y * W[4] + x.z * W[8]  + x.w * W[12];
    float o1 = b[1] + x.x * W[1] + x.y * W[5] + x.z * W[9]  + x.w * W[13];
    float o2 = b[2] + x.x * W[2] + x.y * W[6] + x.z * W[10] + x.w * W[14];
    float o3 = b[3] + x.x * W[3] + x.y * W[7] + x.z * W[11] + x.w * W[15];
    *(float4*)(out + (size_t)e * 4) = make_float4(o0, o1, o2, o3);
}

// ---------------- fused first-message ------------------------------------------
#define MEPB 16
__global__ __launch_bounds__(256) void msg_edge_kernel(
    const float* __restrict__ AB,
    const float* __restrict__ ea, const float* __restrict__ xlg,
    const float* __restrict__ Wc, const float* __restrict__ Wd,
    const float* __restrict__ bmsg,
    const int* __restrict__ srcg, const int* __restrict__ dstg,
    float* __restrict__ h, int Eg)
{
    __shared__ float sWc[16 * H];
    __shared__ float sWd[4 * H];
    __shared__ float sb[H];
    __shared__ float sea[MEPB][16];
    __shared__ float sxl[MEPB][4];
    int tid = threadIdx.x;
    for (int i = tid; i < 16 * H; i += 256) sWc[i] = Wc[i];
    for (int i = tid; i < 4 * H; i += 256) sWd[i] = Wd[i];
    sb[tid] = bmsg[tid];
    int e0 = blockIdx.x * MEPB;
    for (int i = tid; i < MEPB * 16; i += 256) {
        int e = e0 + i / 16;
        if (e < Eg) sea[i / 16][i % 16] = ea[(size_t)e * 16 + (i % 16)];
    }
    for (int i = tid; i < MEPB * 4; i += 256) {
        int e = e0 + i / 4;
        if (e < Eg) sxl[i / 4][i % 4] = xlg[(size_t)e * 4 + (i % 4)];
    }
    __syncthreads();
    int c = tid;
    for (int i = 0; i < MEPB; i++) {
        int e = e0 + i;
        if (e >= Eg) break;
        int s = srcg[e], d = dstg[e];
        float v = AB[(size_t)s * 512 + c] + AB[(size_t)d * 512 + 256 + c] + sb[c];
#pragma unroll
        for (int k = 0; k < 16; k++) v = fmaf(sea[i][k], sWc[k * H + c], v);
#pragma unroll
        for (int k = 0; k < 4; k++) v = fmaf(sxl[i][k], sWd[k * H + c], v);
        h[(size_t)e * H + c] = v;
    }
}

// ---------------- BN coefficient computation -----------------------------------
__global__ void bn_coef_kernel(const double* __restrict__ acc,
                               const float* __restrict__ gamma, const float* __restrict__ beta,
                               float* __restrict__ scale, float* __restrict__ shift, int M)
{
    int c = threadIdx.x;
    double mu = acc[c] / (double)M;
    double var = acc[H + c] / (double)M - mu * mu;
    float inv = rsqrtf((float)var + 1e-5f);
    float sc = gamma[c] * inv;
    scale[c] = sc;
    shift[c] = beta[c] - (float)mu * sc;
}

// ---------------- fused GENConv aggregation (CSR gather, int8 out) -------------
__global__ __launch_bounds__(256) void gen_aggr_kernel(
    const float* __restrict__ x, const float* __restrict__ nbg, const float* __restrict__ ebg,
    const float* __restrict__ Wnb, const float* __restrict__ bnb,
    const float* __restrict__ Web, const float* __restrict__ beb,
    const float* __restrict__ bnscale, const float* __restrict__ bnshift,
    const int* __restrict__ src, const int* __restrict__ rowptr, const int* __restrict__ eidx,
    char* __restrict__ o1, char* __restrict__ o0, float* __restrict__ sav, int use_bn)
{
    __shared__ float sWn[4 * H], sWe[4 * H], sbn[H], sbe[H];
    __shared__ float sred[8];
    int tid = threadIdx.x;
    int lane = tid & 31, wq = tid >> 5;
    for (int i = tid; i < 4 * H; i += 256) { sWn[i] = Wnb[i]; sWe[i] = Web[i]; }
    sbn[tid] = bnb[tid];
    sbe[tid] = beb[tid];
    __syncthreads();
    int d = blockIdx.x, c = tid;
    float sc = 1.f, sh = 0.f;
    if (use_bn) { sc = bnscale[c]; sh = bnshift[c]; }
    int beg = rowptr[d], end = rowptr[d + 1];
    float se = 0.f, sw = 0.f;
    for (int p = beg; p < end; p++) {
        int e = eidx[p];
        int s = src[e];
        float4 nv = *(const float4*)(nbg + (size_t)s * 4);
        float4 ev4 = *(const float4*)(ebg + (size_t)e * 4);
        float nbv = sbn[c];
        nbv = fmaf(nv.x, sWn[c], nbv);
        nbv = fmaf(nv.y, sWn[H + c], nbv);
        nbv = fmaf(nv.z, sWn[2 * H + c], nbv);
        nbv = fmaf(nv.w, sWn[3 * H + c], nbv);
        float ebv = sbe[c];
        ebv = fmaf(ev4.x, sWe[c], ebv);
        ebv = fmaf(ev4.y, sWe[H + c], ebv);
        ebv = fmaf(ev4.z, sWe[2 * H + c], ebv);
        ebv = fmaf(ev4.w, sWe[3 * H + c], ebv);
        float xv = x[(size_t)s * H + c];
        if (use_bn) xv = fmaxf(fmaf(xv, sc, sh), 0.f);
        float mv = fmaxf(xv + nbv + ebv, 0.f) + 1e-7f;
        float ee = expf(fminf(mv, 80.f));
        se += ee;
        sw += ee * mv;
    }
    float xv = x[(size_t)d * H + c];
    if (use_bn) xv = fmaxf(fmaf(xv, sc, sh), 0.f);
    float v = xv + sw / (se + 1e-16f);

    float mx = fabsf(v);
#pragma unroll
    for (int o = 16; o > 0; o >>= 1) mx = fmaxf(mx, __shfl_xor_sync(0xffffffffu, mx, o));
    if (lane == 0) sred[wq] = mx;
    __syncthreads();
    if (tid == 0) {
        float m = 0.f;
#pragma unroll
        for (int i = 0; i < 8; i++) m = fmaxf(m, sred[i]);
        sred[0] = m;
    }
    __syncthreads();
    float rmax = sred[0];
    float inv = (rmax > 0.f) ? 127.f / rmax : 0.f;
    char d1, d0;
    quant2(v, inv, d1, d0);
    o1[(size_t)d * H + c] = d1;
    o0[(size_t)d * H + c] = d0;
    if (tid == 0) sav[d] = rmax * (1.f / 127.f);
}

// ---------------- BatchNorm statistics -----------------------------------------
__global__ void bn_stats_kernel(const float* __restrict__ h, int M, double* __restrict__ acc)
{
    int c = threadIdx.x;
    float s = 0.f, s2 = 0.f;
    for (int r = blockIdx.x; r < M; r += gridDim.x) {
        float v = h[(size_t)r * H + c];
        s += v;
        s2 = fmaf(v, v, s2);
    }
    atomicAdd(&acc[c], (double)s);
    atomicAdd(&acc[H + c], (double)s2);
}

// ---------------- node gather (BN fused, CSR over dst_g) -----------------------
__global__ void node_gather_kernel(const float* __restrict__ h,
                                   const float* __restrict__ bnscale,
                                   const float* __restrict__ bnshift,
                                   const int* __restrict__ rowptr, const int* __restrict__ eidx,
                                   float* __restrict__ node_emb)
{
    int n = blockIdx.x, c = threadIdx.x;
    float sc = bnscale[c], sh = bnshift[c];
    int beg = rowptr[n], end = rowptr[n + 1];
    float acc = 0.f;
    for (int p = beg; p < end; p++) {
        int e = eidx[p];
        acc += fmaf(h[(size_t)e * H + c], sc, sh);
    }
    node_emb[(size_t)n * H + c] = acc;
}

__global__ void pool_kernel(const float* __restrict__ node_emb, const int* __restrict__ batch,
                            float* __restrict__ gsum, float* __restrict__ cnt)
{
    int n = blockIdx.x;
    int c = threadIdx.x;
    int b = batch[n];
    atomicAdd(gsum + (size_t)b * H + c, node_emb[(size_t)n * H + c]);
    if (c == 0) atomicAdd(&cnt[b], 1.0f);
}

__global__ void predict_kernel(const float* __restrict__ gsum, const float* __restrict__ cnt,
                               const float* __restrict__ Wp, const float* __restrict__ bp,
                               float* __restrict__ out)
{
    int g = blockIdx.x, c = threadIdx.x;
    float v = gsum[(size_t)g * H + c] * Wp[c];
    __shared__ float red[8];
#pragma unroll
    for (int o = 16; o > 0; o >>= 1) v += __shfl_down_sync(0xffffffffu, v, o);
    if ((c & 31) == 0) red[c >> 5] = v;
    __syncthreads();
    if (c == 0) {
        float t = 0.f;
#pragma unroll
        for (int i = 0; i < 8; i++) t += red[i];
        out[g] = t / fmaxf(cnt[g], 1.0f) + bp[0];
    }
}

// -------------------------------------------------------------------------------
static void* symA(const void* sym)
{
    void* p = nullptr;
    cudaGetSymbolAddress(&p, sym);
    return p;
}

static void build_csr(const int* dst, int n, int E, int* deg, int* blk,
                      int* rowptr, int* cursor, int* eidx)
{
    int nb = (n + 255) / 256;
    zero_int_kernel<<<nb, 256>>>(deg, n);
    hist_kernel<<<(E + 255) / 256, 256>>>(dst, deg, E);
    scan_block_sums<<<nb, 256>>>(deg, blk, n);
    scan_single_block<<<1, 1024>>>(blk, nb);
    scan_final<<<nb, 256>>>(deg, blk, rowptr, cursor, n, E);
    fill_csr_kernel<<<(E + 255) / 256, 256>>>(dst, cursor, eidx, E);
}

extern "C" void kernel_launch(void* const* d_in, const int* in_sizes, int n_in,
                              void* d_out, int out_size)
{
    const float* x_g       = (const float*)d_in[0];
    const float* ea_g      = (const float*)d_in[1];
    const float* x_lg      = (const float*)d_in[2];
    const float* edb       = (const float*)d_in[3];
    const float* ea_lg     = (const float*)d_in[4];
    const float* W_enc     = (const float*)d_in[5];
    const float* b_enc     = (const float*)d_in[6];
    const float* W_msg     = (const float*)d_in[7];
    const float* b_msg     = (const float*)d_in[8];
    const float* Wg_nb     = (const float*)d_in[9];
    const float* bg_nb     = (const float*)d_in[10];
    const float* Wg_eb     = (const float*)d_in[11];
    const float* bg_eb     = (const float*)d_in[12];
    const float* Wl_nb     = (const float*)d_in[13];
    const float* bl_nb     = (const float*)d_in[14];
    const float* Wl_eb     = (const float*)d_in[15];
    const float* bl_eb     = (const float*)d_in[16];
    const float* W1        = (const float*)d_in[17];
    const float* b1        = (const float*)d_in[18];
    const float* W2        = (const float*)d_in[19];
    const float* b2        = (const float*)d_in[20];
    const float* bn_gamma  = (const float*)d_in[21];
    const float* bn_beta   = (const float*)d_in[22];
    const float* W_pred    = (const float*)d_in[23];
    const float* b_pred    = (const float*)d_in[24];
    const int*   eig       = (const int*)d_in[25];
    const int*   eil       = (const int*)d_in[26];
    const int*   batch     = (const int*)d_in[27];

    int N   = in_sizes[0] / 16;   // 20000
    int Eg  = in_sizes[1] / 16;   // 200000
    int Elg = in_sizes[4] / 4;    // 400000
    const int L = 4;

    cudaFuncSetAttribute(i8_gemm_kernel, cudaFuncAttributeMaxDynamicSharedMemorySize,
                         I8_SMEM);

    float* p_AB   = (float*)symA(g_AB);
    float* p_h    = (float*)symA(g_h);
    float* p_nbg  = (float*)symA(g_nbg);
    float* p_ebg  = (float*)symA(g_ebg);
    float* p_ne   = (float*)symA(g_nodeemb);
    double* p_bnacc = (double*)symA(g_bnacc);
    float* p_bnsc = (float*)symA(g_bnscale);
    float* p_bnsh = (float*)symA(g_bnshift);
    float* p_gsum = (float*)symA(g_gsum);
    float* p_cnt  = (float*)symA(g_cnt);

    int* p_deg    = (int*)symA(g_deg);
    int* p_cursor = (int*)symA(g_cursor);
    int* p_blk    = (int*)symA(g_blk);
    int* p_rp_lg  = (int*)symA(g_rowptr_lg);
    int* p_ei_lg  = (int*)symA(g_eidx_lg);
    int* p_rp_g   = (int*)symA(g_rowptr_g);
    int* p_ei_g   = (int*)symA(g_eidx_g);

    char* p_node1 = (char*)symA(g_node1);
    char* p_node0 = (char*)symA(g_node0);
    float* p_sa_node = (float*)symA(g_sa_node);
    char* p_act1  = (char*)symA(g_act1);
    char* p_act0  = (char*)symA(g_act0);
    float* p_sa_act = (float*)symA(g_sa_act);
    __half* p_hid = (__half*)symA(g_hid);
    char* p_hq1   = (char*)symA(g_hq1);
    char* p_hq0   = (char*)symA(g_hq0);
    float* p_sa_hid = (float*)symA(g_sa_hid);
    int* p_rowmax = (int*)symA(g_rowmax);
    char* p_wq1   = (char*)symA(g_wq1);
    char* p_wq0   = (char*)symA(g_wq0);
    float* p_sbw  = (float*)symA(g_sbw);

    const int* src_g = eig;
    const int* dst_g = eig + Eg;
    const int* src_l = eil;
    const int* dst_l = eil + Elg;

    int mtE = (Eg + 127) / 128;   // 1563
    int mtN = (N + 127) / 128;    // 157

    // --- CSR builds ---
    build_csr(dst_l, Eg, Elg, p_deg, p_blk, p_rp_lg, p_cursor, p_ei_lg);
    build_csr(dst_g, N, Eg, p_deg, p_blk, p_rp_g, p_cursor, p_ei_g);

    // --- weight quantization: msg (2 halves), W1 x4, W2 x4 ---
    wquant_kernel<<<256, 256>>>(W_msg,             p_wq1,         p_wq0,         p_sbw,       256, 256);
    wquant_kernel<<<256, 256>>>(W_msg + 256 * 256, p_wq1 + 65536, p_wq0 + 65536, p_sbw + 256, 256, 256);
    for (int l = 0; l < L; l++) {
        wquant_kernel<<<512, 256>>>(W1 + (size_t)l * 131072,
                                    p_wq1 + (1 + l) * 131072, p_wq0 + (1 + l) * 131072,
                                    p_sbw + 512 + l * 512, 256, 512);
        wquant_kernel<<<256, 256>>>(W2 + (size_t)l * 131072,
                                    p_wq1 + (5 + l) * 131072, p_wq0 + (5 + l) * 131072,
                                    p_sbw + 2560 + l * 256, 512, 256);
    }

    // --- node encoder (int8) + combined msg GEMM (int8, N=512) ---
    enc_kernel<<<N, 256>>>(x_g, W_enc, b_enc, p_node1, p_node0, p_sa_node);
    {
        dim3 grid(4, mtN);
        i8_gemm_kernel<<<grid, 512, I8_SMEM>>>(
            p_node1, p_node0, p_sa_node, p_wq1, p_wq0, p_sbw,
            nullptr, nullptr, p_AB, nullptr, nullptr, N, 512, 256, 0);
    }
    basis4_kernel<<<(Eg + 255) / 256, 256>>>(edb,   Wg_nb, bg_nb, p_nbg, Eg);
    basis4_kernel<<<(Elg + 255) / 256, 256>>>(ea_lg, Wg_eb, bg_eb, p_ebg, Elg);
    msg_edge_kernel<<<(Eg + MEPB - 1) / MEPB, 256>>>(
        p_AB, ea_g, x_lg, W_msg + 512 * H, W_msg + 528 * H, b_msg,
        src_g, dst_g, p_h, Eg);

    // --- 4 GENConv layers ---
    for (int l = 0; l < L; l++) {
        int use_bn = (l > 0) ? 1 : 0;
        if (use_bn) {
            cudaMemsetAsync(p_bnacc, 0, 2 * H * sizeof(double));
            bn_stats_kernel<<<1024, 256>>>(p_h, Eg, p_bnacc);
            bn_coef_kernel<<<1, 256>>>(p_bnacc, bn_gamma + (l - 1) * H, bn_beta + (l - 1) * H,
                                       p_bnsc, p_bnsh, Eg);
        }
        gen_aggr_kernel<<<Eg, 256>>>(
            p_h, p_nbg, p_ebg,
            Wl_nb + l * 4 * H, bl_nb + l * H,
            Wl_eb + l * 4 * H, bl_eb + l * H,
            p_bnsc, p_bnsh, src_l, p_rp_lg, p_ei_lg,
            p_act1, p_act0, p_sa_act, use_bn);

        // GEMM1 (int8): hid = relu(act @ W1 + b1), fp16 out + per-row max
        cudaMemsetAsync(p_rowmax, 0, Eg * sizeof(int));
        {
            dim3 grid(4, mtE);
            i8_gemm_kernel<<<grid, 512, I8_SMEM>>>(
                p_act1, p_act0, p_sa_act,
                p_wq1 + (1 + l) * 131072, p_wq0 + (1 + l) * 131072, p_sbw + 512 + l * 512,
                b1 + l * 512, nullptr, nullptr, p_hid, p_rowmax,
                Eg, 512, 256, 1 | 2 | 8 | 16);
        }
        // quantize hid -> 2-digit int8
        hquant_kernel<<<Eg, 256>>>(p_hid, p_rowmax, p_hq1, p_hq0, p_sa_hid, 512);

        // GEMM2 (int8): h = hid @ W2 + b2 (+ residual for l>0), fp32 out
        {
            dim3 grid(2, mtE);
            i8_gemm_kernel<<<grid, 512, I8_SMEM>>>(
                p_hq1, p_hq0, p_sa_hid,
                p_wq1 + (5 + l) * 131072, p_wq0 + (5 + l) * 131072, p_sbw + 2560 + l * 256,
                b2 + l * 256, (l > 0) ? p_h : nullptr, p_h, nullptr, nullptr,
                Eg, 256, 512, (l > 0) ? (1 | 4) : 1);
        }
    }

    // --- final BN coefs + CSR node gather ---
    cudaMemsetAsync(p_bnacc, 0, 2 * H * sizeof(double));
    bn_stats_kernel<<<1024, 256>>>(p_h, Eg, p_bnacc);
    bn_coef_kernel<<<1, 256>>>(p_bnacc, bn_gamma + 3 * H, bn_beta + 3 * H, p_bnsc, p_bnsh, Eg);

    node_gather_kernel<<<N, 256>>>(p_h, p_bnsc, p_bnsh, p_rp_g, p_ei_g, p_ne);

    cudaMemsetAsync(p_gsum, 0, NGRAPH * H * sizeof(float));
    cudaMemsetAsync(p_cnt,  0, NGRAPH * sizeof(float));
    pool_kernel<<<N, 256>>>(p_ne, batch, p_gsum, p_cnt);
    predict_kernel<<<NGRAPH, 256>>>(p_gsum, p_cnt, W_pred, b_pred, (float*)d_out);
}

// round 10
// speedup vs baseline: 1.3735x; 1.3735x over previous
#include <cuda_runtime.h>
#include <cuda_fp16.h>
#include <cstdint>

#define H 256
#define NGRAPH 128
#define MAXN   20224
#define MAXEG  200192
#define MAXELG 400128

// ---------------- scratch ----------------
__device__ float g_AB[(size_t)MAXN * 512];
__device__ float g_h[(size_t)MAXEG * H];
__device__ float g_nbg[(size_t)MAXEG * 4];
__device__ float g_ebg[(size_t)MAXELG * 4];
__device__ float g_nodeemb[(size_t)MAXN * H];
__device__ double g_bnacc[2 * H];
__device__ float g_bnscale[H];
__device__ float g_bnshift[H];
__device__ float g_gsum[NGRAPH * H];
__device__ float g_cnt[NGRAPH];

// CSR scratch
__device__ int g_deg[MAXEG];
__device__ int g_cursor[MAXEG];
__device__ int g_blk[1024];
__device__ int g_rowptr_lg[MAXEG + 1];
__device__ int g_eidx_lg[MAXELG];
__device__ int g_rowptr_g[MAXN + 1];
__device__ int g_eidx_g[MAXEG];

// fp16 activation buffers (pad rows never written -> stay zero)
__device__ __half g_node[(size_t)MAXN * H];
__device__ __half g_act[(size_t)MAXEG * H];
__device__ __half g_hid[(size_t)MAXEG * 2 * H];

// transposed/split fp16 weights arena
#define OFF_WMSG 0
#define OFF_W1T  (512 * 256)
#define OFF_W2T  (OFF_W1T + 4 * 131072)
#define WT_TOTAL (OFF_W2T + 4 * 131072)
__device__ __half g_wthi[WT_TOTAL];
__device__ __half g_wtlo[WT_TOTAL];

// ======================= helpers =======================
__device__ __forceinline__ uint32_t smem_u32(const void* p) {
    uint32_t a;
    asm("{ .reg .u64 t; cvta.to.shared.u64 t, %1; cvt.u32.u64 %0, t; }" : "=r"(a) : "l"(p));
    return a;
}
#define CP16(dst, src) \
    asm volatile("cp.async.cg.shared.global [%0], [%1], 16;" :: "r"(dst), "l"(src) : "memory")
#define CP_COMMIT() asm volatile("cp.async.commit_group;" ::: "memory")
#define CP_WAIT1()  asm volatile("cp.async.wait_group 1;" ::: "memory")
#define CP_WAIT0()  asm volatile("cp.async.wait_group 0;" ::: "memory")

__device__ __forceinline__ void ldm4(uint32_t (&r)[4], uint32_t addr) {
    asm volatile("ldmatrix.sync.aligned.m8n8.x4.shared.b16 {%0,%1,%2,%3}, [%4];"
                 : "=r"(r[0]), "=r"(r[1]), "=r"(r[2]), "=r"(r[3]) : "r"(addr));
}
__device__ __forceinline__ void mma_f16(float (&d)[4], const uint32_t (&a)[4], const uint32_t* b) {
    asm volatile(
        "mma.sync.aligned.m16n8k16.row.col.f32.f16.f16.f32 "
        "{%0,%1,%2,%3}, {%4,%5,%6,%7}, {%8,%9}, {%0,%1,%2,%3};"
        : "+f"(d[0]), "+f"(d[1]), "+f"(d[2]), "+f"(d[3])
        : "r"(a[0]), "r"(a[1]), "r"(a[2]), "r"(a[3]), "r"(b[0]), "r"(b[1]));
}

// ======================= CSR build kernels =======================
__global__ void zero_int_kernel(int* a, int n)
{
    int i = blockIdx.x * 256 + threadIdx.x;
    if (i < n) a[i] = 0;
}
__global__ void hist_kernel(const int* __restrict__ dst, int* __restrict__ deg, int E)
{
    int i = blockIdx.x * 256 + threadIdx.x;
    if (i < E) atomicAdd(&deg[dst[i]], 1);
}
__global__ void scan_block_sums(const int* __restrict__ deg, int* __restrict__ blk, int n)
{
    __shared__ int sd[256];
    int t = threadIdx.x;
    int i = blockIdx.x * 256 + t;
    sd[t] = (i < n) ? deg[i] : 0;
    __syncthreads();
    for (int o = 128; o > 0; o >>= 1) {
        if (t < o) sd[t] += sd[t + o];
        __syncthreads();
    }
    if (t == 0) blk[blockIdx.x] = sd[0];
}
__global__ void scan_single_block(int* blk, int nb)
{
    __shared__ int tmp[1024];
    int t = threadIdx.x;
    int v = (t < nb) ? blk[t] : 0;
    tmp[t] = v;
    __syncthreads();
    for (int o = 1; o < 1024; o <<= 1) {
        int u = (t >= o) ? tmp[t - o] : 0;
        __syncthreads();
        tmp[t] += u;
        __syncthreads();
    }
    if (t < nb) blk[t] = tmp[t] - v;
}
__global__ void scan_final(const int* __restrict__ deg, const int* __restrict__ blk,
                           int* __restrict__ rowptr, int* __restrict__ cursor, int n, int E)
{
    __shared__ int tmp[256];
    int t = threadIdx.x;
    int i = blockIdx.x * 256 + t;
    int v = (i < n) ? deg[i] : 0;
    tmp[t] = v;
    __syncthreads();
    for (int o = 1; o < 256; o <<= 1) {
        int u = (t >= o) ? tmp[t - o] : 0;
        __syncthreads();
        tmp[t] += u;
        __syncthreads();
    }
    int excl = tmp[t] - v + blk[blockIdx.x];
    if (i < n) { rowptr[i] = excl; cursor[i] = excl; }
    if (blockIdx.x == 0 && t == 0) rowptr[n] = E;
}
__global__ void fill_csr_kernel(const int* __restrict__ dst, int* __restrict__ cursor,
                                int* __restrict__ eidx, int E)
{
    int e = blockIdx.x * 256 + threadIdx.x;
    if (e < E) {
        int p = atomicAdd(&cursor[dst[e]], 1);
        eidx[p] = e;
    }
}

// ======================= mma.sync 2-term fp16 GEMM =======================
// C[M,N] = A[M,K] @ W[K,N]; A fp16 [M,K] row-major, W transposed split fp16
// (Bhi,Blo) [N,K] row-major.  C = A*Bhi + A*Blo (fp32 acc).
// CTA 128x128, 8 warps of 64x32, BK=32, 3 stages, 2 CTAs/SM.
// Grid: blockIdx.x = n-tile (fast) -> consecutive CTAs share the A m-tile (L2 reuse).
// flags: 1=bias, 2=relu, 4=residual(fp32 [M,N]), 8=fp16 out (else fp32 out)
#define RB 80
#define TILE_B (128 * RB)
#define SO_A   0
#define SO_BHI (1 * TILE_B)
#define SO_BLO (2 * TILE_B)
#define STAGE_B (3 * TILE_B)        // 30720
#define GEMM_SMEM (3 * STAGE_B)     // 92160

__device__ __forceinline__ void load_stage(uint32_t sbase,
    const __half* __restrict__ A, const __half* __restrict__ B_hi,
    const __half* __restrict__ B_lo,
    int K, int m0, int n0, int k0, int tid)
{
#pragma unroll
    for (int i = 0; i < 2; i++) {
        int g = tid + i * 256;
        int row = g >> 2, ch = g & 3;
        uint32_t so = (uint32_t)row * RB + (uint32_t)ch * 16;
        size_t ao = (size_t)(m0 + row) * K + k0 + ch * 8;
        size_t bo = (size_t)(n0 + row) * K + k0 + ch * 8;
        CP16(sbase + SO_A + so, A + ao);
        CP16(sbase + SO_BHI + so, B_hi + bo);
        CP16(sbase + SO_BLO + so, B_lo + bo);
    }
}

__global__ __launch_bounds__(256, 2) void mma_gemm_kernel(
    const __half* __restrict__ A,
    const __half* __restrict__ Bhi, const __half* __restrict__ Blo,
    const float* __restrict__ bias, const float* __restrict__ res,
    float* __restrict__ Cf, __half* __restrict__ Ch,
    int M, int N, int K, int flags)
{
    extern __shared__ __align__(128) char smem[];
    uint32_t sb = smem_u32(smem);
    int tid = threadIdx.x;
    int wid = tid >> 5, lane = tid & 31;
    int m0 = blockIdx.y * 128, n0 = blockIdx.x * 128;
    int nk = K >> 5;

    load_stage(sb, A, Bhi, Blo, K, m0, n0, 0, tid);
    CP_COMMIT();
    load_stage(sb + STAGE_B, A, Bhi, Blo, K, m0, n0, 32, tid);
    CP_COMMIT();

    float acc[4][4][4];
#pragma unroll
    for (int i = 0; i < 4; i++)
#pragma unroll
        for (int j = 0; j < 4; j++)
#pragma unroll
            for (int q = 0; q < 4; q++) acc[i][j][q] = 0.f;

    int mo = (wid & 1) * 64, no = (wid >> 1) * 32;
    int a_row = mo + (lane & 15);
    int a_k8  = lane >> 4;
    int b_row = ((lane >> 4) << 3) + (lane & 7);
    int b_k8  = (lane >> 3) & 1;

    for (int k = 0; k < nk; k++) {
        if (k == nk - 1) { CP_WAIT0(); } else { CP_WAIT1(); }
        __syncthreads();
        uint32_t base = sb + (uint32_t)(k % 3) * STAGE_B;
        if (k + 2 < nk)
            load_stage(sb + (uint32_t)((k + 2) % 3) * STAGE_B, A, Bhi, Blo,
                       K, m0, n0, (k + 2) * 32, tid);
        CP_COMMIT();
#pragma unroll
        for (int k16 = 0; k16 < 2; k16++) {
            int kk8 = k16 * 2;
            uint32_t ah[4][4];
#pragma unroll
            for (int i = 0; i < 4; i++) {
                uint32_t aaddr = base + SO_A + (uint32_t)(a_row + i * 16) * RB
                               + (uint32_t)(kk8 + a_k8) * 16;
                ldm4(ah[i], aaddr);
            }
#pragma unroll
            for (int j = 0; j < 2; j++) {
                uint32_t bh[4], bl[4];
                uint32_t baddr = base + SO_BHI + (uint32_t)(no + j * 16 + b_row) * RB
                               + (uint32_t)(kk8 + b_k8) * 16;
                ldm4(bh, baddr);
                ldm4(bl, baddr + (SO_BLO - SO_BHI));
#pragma unroll
                for (int i = 0; i < 4; i++) {
                    mma_f16(acc[i][2 * j],     ah[i], &bh[0]);
                    mma_f16(acc[i][2 * j + 1], ah[i], &bh[2]);
                    mma_f16(acc[i][2 * j],     ah[i], &bl[0]);
                    mma_f16(acc[i][2 * j + 1], ah[i], &bl[2]);
                }
            }
        }
    }

    // epilogue
#pragma unroll
    for (int i = 0; i < 4; i++) {
        int r0 = m0 + mo + i * 16 + (lane >> 2);
#pragma unroll
        for (int half = 0; half < 2; half++) {
            int r = r0 + half * 8;
            if (r >= M) continue;
#pragma unroll
            for (int nb = 0; nb < 4; nb++) {
                int col = n0 + no + nb * 8 + 2 * (lane & 3);
                float v0 = acc[i][nb][half * 2 + 0];
                float v1 = acc[i][nb][half * 2 + 1];
                if (flags & 1) { v0 += bias[col]; v1 += bias[col + 1]; }
                if (flags & 4) {
                    float2 t = *(const float2*)(res + (size_t)r * N + col);
                    v0 += t.x; v1 += t.y;
                }
                if (flags & 2) { v0 = fmaxf(v0, 0.f); v1 = fmaxf(v1, 0.f); }
                if (flags & 8) {
                    *(__half2*)(Ch + (size_t)r * N + col) =
                        __halves2half2(__float2half(v0), __float2half(v1));
                } else {
                    *(float2*)(Cf + (size_t)r * N + col) = make_float2(v0, v1);
                }
            }
        }
    }
}

// ---------------- weight transpose+split (fp16 hi/lo) --------------------------
__global__ void tsplit_kernel(const float* __restrict__ W,
                              __half* __restrict__ thi, __half* __restrict__ tlo,
                              int K, int N)
{
    int idx = blockIdx.x * 256 + threadIdx.x;
    if (idx >= K * N) return;
    int k = idx / N, n = idx % N;
    float w = W[idx];
    __half hi = __float2half(w);
    __half lo = __float2half(w - __half2float(hi));
    thi[(size_t)n * K + k] = hi;
    tlo[(size_t)n * K + k] = lo;
}

// ---------------- node encoder (fp16 out) --------------------------------------
__global__ void enc_kernel(const float* __restrict__ xg, const float* __restrict__ W,
                           const float* __restrict__ b, __half* __restrict__ out)
{
    __shared__ float sx[16];
    int n = blockIdx.x, c = threadIdx.x;
    if (c < 16) sx[c] = xg[(size_t)n * 16 + c];
    __syncthreads();
    float v = b[c];
#pragma unroll
    for (int k = 0; k < 16; k++) v = fmaf(sx[k], W[k * H + c], v);
    out[(size_t)n * H + c] = __float2half(v);
}

// ---------------- tiny [E,4]@[4,4]+b projection --------------------------------
__global__ void basis4_kernel(const float* __restrict__ in, const float* __restrict__ W,
                              const float* __restrict__ b, float* __restrict__ out, int E)
{
    int e = blockIdx.x * blockDim.x + threadIdx.x;
    if (e >= E) return;
    float4 x = *(const float4*)(in + (size_t)e * 4);
    float o0 = b[0] + x.x * W[0] + x.y * W[4] + x.z * W[8]  + x.w * W[12];
    float o1 = b[1] + x.x * W[1] + x.y * W[5] + x.z * W[9]  + x.w * W[13];
    float o2 = b[2] + x.x * W[2] + x.y * W[6] + x.z * W[10] + x.w * W[14];
    float o3 = b[3] + x.x * W[3] + x.y * W[7] + x.z * W[11] + x.w * W[15];
    *(float4*)(out + (size_t)e * 4) = make_float4(o0, o1, o2, o3);
}

// ---------------- fused first-message ------------------------------------------
#define MEPB 16
__global__ __launch_bounds__(256) void msg_edge_kernel(
    const float* __restrict__ AB,
    const float* __restrict__ ea, const float* __restrict__ xlg,
    const float* __restrict__ Wc, const float* __restrict__ Wd,
    const float* __restrict__ bmsg,
    const int* __restrict__ srcg, const int* __restrict__ dstg,
    float* __restrict__ h, int Eg)
{
    __shared__ float sWc[16 * H];
    __shared__ float sWd[4 * H];
    __shared__ float sb[H];
    __shared__ float sea[MEPB][16];
    __shared__ float sxl[MEPB][4];
    int tid = threadIdx.x;
    for (int i = tid; i < 16 * H; i += 256) sWc[i] = Wc[i];
    for (int i = tid; i < 4 * H; i += 256) sWd[i] = Wd[i];
    sb[tid] = bmsg[tid];
    int e0 = blockIdx.x * MEPB;
    for (int i = tid; i < MEPB * 16; i += 256) {
        int e = e0 + i / 16;
        if (e < Eg) sea[i / 16][i % 16] = ea[(size_t)e * 16 + (i % 16)];
    }
    for (int i = tid; i < MEPB * 4; i += 256) {
        int e = e0 + i / 4;
        if (e < Eg) sxl[i / 4][i % 4] = xlg[(size_t)e * 4 + (i % 4)];
    }
    __syncthreads();
    int c = tid;
    for (int i = 0; i < MEPB; i++) {
        int e = e0 + i;
        if (e >= Eg) break;
        int s = srcg[e], d = dstg[e];
        float v = AB[(size_t)s * 512 + c] + AB[(size_t)d * 512 + 256 + c] + sb[c];
#pragma unroll
        for (int k = 0; k < 16; k++) v = fmaf(sea[i][k], sWc[k * H + c], v);
#pragma unroll
        for (int k = 0; k < 4; k++) v = fmaf(sxl[i][k], sWd[k * H + c], v);
        h[(size_t)e * H + c] = v;
    }
}

// ---------------- BN coefficient computation -----------------------------------
__global__ void bn_coef_kernel(const double* __restrict__ acc,
                               const float* __restrict__ gamma, const float* __restrict__ beta,
                               float* __restrict__ scale, float* __restrict__ shift, int M)
{
    int c = threadIdx.x;
    double mu = acc[c] / (double)M;
    double var = acc[H + c] / (double)M - mu * mu;
    float inv = rsqrtf((float)var + 1e-5f);
    float sc = gamma[c] * inv;
    scale[c] = sc;
    shift[c] = beta[c] - (float)mu * sc;
}

// ---------------- fused GENConv aggregation (CSR gather, fp16 out) -------------
// 8 dst rows per block: weight smem fill amortized 8x.
#define RPB 8
__global__ __launch_bounds__(256) void gen_aggr_kernel(
    const float* __restrict__ x, const float* __restrict__ nbg, const float* __restrict__ ebg,
    const float* __restrict__ Wnb, const float* __restrict__ bnb,
    const float* __restrict__ Web, const float* __restrict__ beb,
    const float* __restrict__ bnscale, const float* __restrict__ bnshift,
    const int* __restrict__ src, const int* __restrict__ rowptr, const int* __restrict__ eidx,
    __half* __restrict__ aout, int E, int use_bn)
{
    __shared__ float sWn[4 * H], sWe[4 * H], sbn[H], sbe[H];
    int tid = threadIdx.x;
    for (int i = tid; i < 4 * H; i += 256) { sWn[i] = Wnb[i]; sWe[i] = Web[i]; }
    sbn[tid] = bnb[tid];
    sbe[tid] = beb[tid];
    __syncthreads();
    int c = tid;
    float sc = 1.f, sh = 0.f;
    if (use_bn) { sc = bnscale[c]; sh = bnshift[c]; }
    int d0 = blockIdx.x * RPB;
#pragma unroll
    for (int rr = 0; rr < RPB; rr++) {
        int d = d0 + rr;
        if (d >= E) break;
        int beg = rowptr[d], end = rowptr[d + 1];
        float se = 0.f, sw = 0.f;
        for (int p = beg; p < end; p++) {
            int e = eidx[p];
            int s = src[e];
            float4 nv = *(const float4*)(nbg + (size_t)s * 4);
            float4 ev4 = *(const float4*)(ebg + (size_t)e * 4);
            float nbv = sbn[c];
            nbv = fmaf(nv.x, sWn[c], nbv);
            nbv = fmaf(nv.y, sWn[H + c], nbv);
            nbv = fmaf(nv.z, sWn[2 * H + c], nbv);
            nbv = fmaf(nv.w, sWn[3 * H + c], nbv);
            float ebv = sbe[c];
            ebv = fmaf(ev4.x, sWe[c], ebv);
            ebv = fmaf(ev4.y, sWe[H + c], ebv);
            ebv = fmaf(ev4.z, sWe[2 * H + c], ebv);
            ebv = fmaf(ev4.w, sWe[3 * H + c], ebv);
            float xv = x[(size_t)s * H + c];
            if (use_bn) xv = fmaxf(fmaf(xv, sc, sh), 0.f);
            float mv = fmaxf(xv + nbv + ebv, 0.f) + 1e-7f;
            float ee = expf(fminf(mv, 80.f));
            se += ee;
            sw += ee * mv;
        }
        float xv = x[(size_t)d * H + c];
        if (use_bn) xv = fmaxf(fmaf(xv, sc, sh), 0.f);
        float v = xv + sw / (se + 1e-16f);
        aout[(size_t)d * H + c] = __float2half(v);
    }
}

// ---------------- BatchNorm statistics -----------------------------------------
__global__ void bn_stats_kernel(const float* __restrict__ h, int M, double* __restrict__ acc)
{
    int c = threadIdx.x;
    float s = 0.f, s2 = 0.f;
    for (int r = blockIdx.x; r < M; r += gridDim.x) {
        float v = h[(size_t)r * H + c];
        s += v;
        s2 = fmaf(v, v, s2);
    }
    atomicAdd(&acc[c], (double)s);
    atomicAdd(&acc[H + c], (double)s2);
}

// ---------------- node gather (BN fused, CSR over dst_g) -----------------------
__global__ void node_gather_kernel(const float* __restrict__ h,
                                   const float* __restrict__ bnscale,
                                   const float* __restrict__ bnshift,
                                   const int* __restrict__ rowptr, const int* __restrict__ eidx,
                                   float* __restrict__ node_emb)
{
    int n = blockIdx.x, c = threadIdx.x;
    float sc = bnscale[c], sh = bnshift[c];
    int beg = rowptr[n], end = rowptr[n + 1];
    float acc = 0.f;
    for (int p = beg; p < end; p++) {
        int e = eidx[p];
        acc += fmaf(h[(size_t)e * H + c], sc, sh);
    }
    node_emb[(size_t)n * H + c] = acc;
}

__global__ void pool_kernel(const float* __restrict__ node_emb, const int* __restrict__ batch,
                            float* __restrict__ gsum, float* __restrict__ cnt)
{
    int n = blockIdx.x;
    int c = threadIdx.x;
    int b = batch[n];
    atomicAdd(gsum + (size_t)b * H + c, node_emb[(size_t)n * H + c]);
    if (c == 0) atomicAdd(&cnt[b], 1.0f);
}

__global__ void predict_kernel(const float* __restrict__ gsum, const float* __restrict__ cnt,
                               const float* __restrict__ Wp, const float* __restrict__ bp,
                               float* __restrict__ out)
{
    int g = blockIdx.x, c = threadIdx.x;
    float v = gsum[(size_t)g * H + c] * Wp[c];
    __shared__ float red[8];
#pragma unroll
    for (int o = 16; o > 0; o >>= 1) v += __shfl_down_sync(0xffffffffu, v, o);
    if ((c & 31) == 0) red[c >> 5] = v;
    __syncthreads();
    if (c == 0) {
        float t = 0.f;
#pragma unroll
        for (int i = 0; i < 8; i++) t += red[i];
        out[g] = t / fmaxf(cnt[g], 1.0f) + bp[0];
    }
}

// -------------------------------------------------------------------------------
static void* symA(const void* sym)
{
    void* p = nullptr;
    cudaGetSymbolAddress(&p, sym);
    return p;
}

static void build_csr(const int* dst, int n, int E, int* deg, int* blk,
                      int* rowptr, int* cursor, int* eidx)
{
    int nb = (n + 255) / 256;
    zero_int_kernel<<<nb, 256>>>(deg, n);
    hist_kernel<<<(E + 255) / 256, 256>>>(dst, deg, E);
    scan_block_sums<<<nb, 256>>>(deg, blk, n);
    scan_single_block<<<1, 1024>>>(blk, nb);
    scan_final<<<nb, 256>>>(deg, blk, rowptr, cursor, n, E);
    fill_csr_kernel<<<(E + 255) / 256, 256>>>(dst, cursor, eidx, E);
}

extern "C" void kernel_launch(void* const* d_in, const int* in_sizes, int n_in,
                              void* d_out, int out_size)
{
    const float* x_g       = (const float*)d_in[0];
    const float* ea_g      = (const float*)d_in[1];
    const float* x_lg      = (const float*)d_in[2];
    const float* edb       = (const float*)d_in[3];
    const float* ea_lg     = (const float*)d_in[4];
    const float* W_enc     = (const float*)d_in[5];
    const float* b_enc     = (const float*)d_in[6];
    const float* W_msg     = (const float*)d_in[7];
    const float* b_msg     = (const float*)d_in[8];
    const float* Wg_nb     = (const float*)d_in[9];
    const float* bg_nb     = (const float*)d_in[10];
    const float* Wg_eb     = (const float*)d_in[11];
    const float* bg_eb     = (const float*)d_in[12];
    const float* Wl_nb     = (const float*)d_in[13];
    const float* bl_nb     = (const float*)d_in[14];
    const float* Wl_eb     = (const float*)d_in[15];
    const float* bl_eb     = (const float*)d_in[16];
    const float* W1        = (const float*)d_in[17];
    const float* b1        = (const float*)d_in[18];
    const float* W2        = (const float*)d_in[19];
    const float* b2        = (const float*)d_in[20];
    const float* bn_gamma  = (const float*)d_in[21];
    const float* bn_beta   = (const float*)d_in[22];
    const float* W_pred    = (const float*)d_in[23];
    const float* b_pred    = (const float*)d_in[24];
    const int*   eig       = (const int*)d_in[25];
    const int*   eil       = (const int*)d_in[26];
    const int*   batch     = (const int*)d_in[27];

    int N   = in_sizes[0] / 16;   // 20000
    int Eg  = in_sizes[1] / 16;   // 200000
    int Elg = in_sizes[4] / 4;    // 400000
    const int L = 4;

    cudaFuncSetAttribute(mma_gemm_kernel, cudaFuncAttributeMaxDynamicSharedMemorySize,
                         GEMM_SMEM);

    float* p_AB   = (float*)symA(g_AB);
    float* p_h    = (float*)symA(g_h);
    float* p_nbg  = (float*)symA(g_nbg);
    float* p_ebg  = (float*)symA(g_ebg);
    float* p_ne   = (float*)symA(g_nodeemb);
    double* p_bnacc = (double*)symA(g_bnacc);
    float* p_bnsc = (float*)symA(g_bnscale);
    float* p_bnsh = (float*)symA(g_bnshift);
    float* p_gsum = (float*)symA(g_gsum);
    float* p_cnt  = (float*)symA(g_cnt);

    int* p_deg    = (int*)symA(g_deg);
    int* p_cursor = (int*)symA(g_cursor);
    int* p_blk    = (int*)symA(g_blk);
    int* p_rp_lg  = (int*)symA(g_rowptr_lg);
    int* p_ei_lg  = (int*)symA(g_eidx_lg);
    int* p_rp_g   = (int*)symA(g_rowptr_g);
    int* p_ei_g   = (int*)symA(g_eidx_g);

    __half* p_node = (__half*)symA(g_node);
    __half* p_act  = (__half*)symA(g_act);
    __half* p_hid  = (__half*)symA(g_hid);
    __half* p_wthi = (__half*)symA(g_wthi);
    __half* p_wtlo = (__half*)symA(g_wtlo);

    const int* src_g = eig;
    const int* dst_g = eig + Eg;
    const int* src_l = eil;
    const int* dst_l = eil + Elg;

    int mtE = (Eg + 127) / 128;   // 1563
    int mtN = (N + 127) / 128;    // 157

    // --- CSR builds ---
    build_csr(dst_l, Eg, Elg, p_deg, p_blk, p_rp_lg, p_cursor, p_ei_lg);
    build_csr(dst_g, N, Eg, p_deg, p_blk, p_rp_g, p_cursor, p_ei_g);

    // --- weight transpose + split ---
    tsplit_kernel<<<(65536 + 255) / 256, 256>>>(W_msg,           p_wthi + OFF_WMSG,         p_wtlo + OFF_WMSG,         256, 256);
    tsplit_kernel<<<(65536 + 255) / 256, 256>>>(W_msg + 256 * H, p_wthi + OFF_WMSG + 65536, p_wtlo + OFF_WMSG + 65536, 256, 256);
    for (int l = 0; l < L; l++) {
        tsplit_kernel<<<(131072 + 255) / 256, 256>>>(
            W1 + (size_t)l * 131072, p_wthi + OFF_W1T + l * 131072, p_wtlo + OFF_W1T + l * 131072, 256, 512);
        tsplit_kernel<<<(131072 + 255) / 256, 256>>>(
            W2 + (size_t)l * 131072, p_wthi + OFF_W2T + l * 131072, p_wtlo + OFF_W2T + l * 131072, 512, 256);
    }

    // --- node encoder + combined msg GEMM (N=512) ---
    enc_kernel<<<N, 256>>>(x_g, W_enc, b_enc, p_node);
    {
        dim3 grid(4, mtN);   // n fast
        mma_gemm_kernel<<<grid, 256, GEMM_SMEM>>>(
            p_node, p_wthi + OFF_WMSG, p_wtlo + OFF_WMSG,
            nullptr, nullptr, p_AB, nullptr, N, 512, 256, 0);
    }
    basis4_kernel<<<(Eg + 255) / 256, 256>>>(edb,   Wg_nb, bg_nb, p_nbg, Eg);
    basis4_kernel<<<(Elg + 255) / 256, 256>>>(ea_lg, Wg_eb, bg_eb, p_ebg, Elg);
    msg_edge_kernel<<<(Eg + MEPB - 1) / MEPB, 256>>>(
        p_AB, ea_g, x_lg, W_msg + 512 * H, W_msg + 528 * H, b_msg,
        src_g, dst_g, p_h, Eg);

    // --- 4 GENConv layers ---
    for (int l = 0; l < L; l++) {
        int use_bn = (l > 0) ? 1 : 0;
        if (use_bn) {
            cudaMemsetAsync(p_bnacc, 0, 2 * H * sizeof(double));
            bn_stats_kernel<<<1024, 256>>>(p_h, Eg, p_bnacc);
            bn_coef_kernel<<<1, 256>>>(p_bnacc, bn_gamma + (l - 1) * H, bn_beta + (l - 1) * H,
                                       p_bnsc, p_bnsh, Eg);
        }
        gen_aggr_kernel<<<(Eg + RPB - 1) / RPB, 256>>>(
            p_h, p_nbg, p_ebg,
            Wl_nb + l * 4 * H, bl_nb + l * H,
            Wl_eb + l * 4 * H, bl_eb + l * H,
            p_bnsc, p_bnsh, src_l, p_rp_lg, p_ei_lg,
            p_act, Eg, use_bn);

        // GEMM1: hid = relu(act @ W1 + b1), fp16 out
        {
            dim3 grid(4, mtE);   // n fast
            mma_gemm_kernel<<<grid, 256, GEMM_SMEM>>>(
                p_act, p_wthi + OFF_W1T + l * 131072, p_wtlo + OFF_W1T + l * 131072,
                b1 + l * 512, nullptr, nullptr, p_hid,
                Eg, 512, 256, 1 | 2 | 8);
        }
        // GEMM2: h = hid @ W2 + b2 (+ residual for l>0), fp32 out
        {
            dim3 grid(2, mtE);   // n fast
            mma_gemm_kernel<<<grid, 256, GEMM_SMEM>>>(
                p_hid, p_wthi + OFF_W2T + l * 131072, p_wtlo + OFF_W2T + l * 131072,
                b2 + l * 256, (l > 0) ? p_h : nullptr, p_h, nullptr,
                Eg, 256, 512, (l > 0) ? (1 | 4) : 1);
        }
    }

    // --- final BN coefs + CSR node gather ---
    cudaMemsetAsync(p_bnacc, 0, 2 * H * sizeof(double));
    bn_stats_kernel<<<1024, 256>>>(p_h, Eg, p_bnacc);
    bn_coef_kernel<<<1, 256>>>(p_bnacc, bn_gamma + 3 * H, bn_beta + 3 * H, p_bnsc, p_bnsh, Eg);

    node_gather_kernel<<<N, 256>>>(p_h, p_bnsc, p_bnsh, p_rp_g, p_ei_g, p_ne);

    cudaMemsetAsync(p_gsum, 0, NGRAPH * H * sizeof(float));
    cudaMemsetAsync(p_cnt,  0, NGRAPH * sizeof(float));
    pool_kernel<<<N, 256>>>(p_ne, batch, p_gsum, p_cnt);
    predict_kernel<<<NGRAPH, 256>>>(p_gsum, p_cnt, W_pred, b_pred, (float*)d_out);
}

// round 11
// speedup vs baseline: 1.3973x; 1.0174x over previous
#include <cuda_runtime.h>
#include <cuda_fp16.h>
#include <cstdint>

#define H 256
#define NGRAPH 128
#define MAXN   20224
#define MAXEG  200192
#define MAXELG 400128

// ---------------- scratch ----------------
__device__ float g_AB[(size_t)MAXN * 512];
__device__ float g_h[(size_t)MAXEG * H];
__device__ float g_nbg[(size_t)MAXEG * 4];
__device__ float g_ebg[(size_t)MAXELG * 4];
__device__ float g_nodeemb[(size_t)MAXN * H];
__device__ double g_bnacc[2 * H];
__device__ float g_bnscale[H];
__device__ float g_bnshift[H];
__device__ float g_gsum[NGRAPH * H];
__device__ float g_cnt[NGRAPH];

// CSR scratch
__device__ int g_deg[MAXEG];
__device__ int g_cursor[MAXEG];
__device__ int g_blk[1024];
__device__ int g_rowptr_lg[MAXEG + 1];
__device__ int g_eidx_lg[MAXELG];
__device__ int g_rowptr_g[MAXN + 1];
__device__ int g_eidx_g[MAXEG];

// fp16 activation buffers (pad rows never written -> stay zero)
__device__ __half g_node[(size_t)MAXN * H];
__device__ __half g_act[(size_t)MAXEG * H];
__device__ __half g_hid[(size_t)MAXEG * 2 * H];

// transposed/split fp16 weights arena
#define OFF_WMSG 0
#define OFF_W1T  (512 * 256)
#define OFF_W2T  (OFF_W1T + 4 * 131072)
#define WT_TOTAL (OFF_W2T + 4 * 131072)
__device__ __half g_wthi[WT_TOTAL];
__device__ __half g_wtlo[WT_TOTAL];

// ======================= helpers =======================
__device__ __forceinline__ uint32_t smem_u32(const void* p) {
    uint32_t a;
    asm("{ .reg .u64 t; cvta.to.shared.u64 t, %1; cvt.u32.u64 %0, t; }" : "=r"(a) : "l"(p));
    return a;
}
#define CP16(dst, src) \
    asm volatile("cp.async.cg.shared.global [%0], [%1], 16;" :: "r"(dst), "l"(src) : "memory")
#define CP_COMMIT() asm volatile("cp.async.commit_group;" ::: "memory")
#define CP_WAIT1()  asm volatile("cp.async.wait_group 1;" ::: "memory")
#define CP_WAIT0()  asm volatile("cp.async.wait_group 0;" ::: "memory")

__device__ __forceinline__ void ldm4(uint32_t (&r)[4], uint32_t addr) {
    asm volatile("ldmatrix.sync.aligned.m8n8.x4.shared.b16 {%0,%1,%2,%3}, [%4];"
                 : "=r"(r[0]), "=r"(r[1]), "=r"(r[2]), "=r"(r[3]) : "r"(addr));
}
__device__ __forceinline__ void mma_f16(float (&d)[4], const uint32_t (&a)[4], const uint32_t* b) {
    asm volatile(
        "mma.sync.aligned.m16n8k16.row.col.f32.f16.f16.f32 "
        "{%0,%1,%2,%3}, {%4,%5,%6,%7}, {%8,%9}, {%0,%1,%2,%3};"
        : "+f"(d[0]), "+f"(d[1]), "+f"(d[2]), "+f"(d[3])
        : "r"(a[0]), "r"(a[1]), "r"(a[2]), "r"(a[3]), "r"(b[0]), "r"(b[1]));
}

// ======================= CSR build kernels =======================
__global__ void zero_int_kernel(int* a, int n)
{
    int i = blockIdx.x * 256 + threadIdx.x;
    if (i < n) a[i] = 0;
}
__global__ void hist_kernel(const int* __restrict__ dst, int* __restrict__ deg, int E)
{
    int i = blockIdx.x * 256 + threadIdx.x;
    if (i < E) atomicAdd(&deg[dst[i]], 1);
}
__global__ void scan_block_sums(const int* __restrict__ deg, int* __restrict__ blk, int n)
{
    __shared__ int sd[256];
    int t = threadIdx.x;
    int i = blockIdx.x * 256 + t;
    sd[t] = (i < n) ? deg[i] : 0;
    __syncthreads();
    for (int o = 128; o > 0; o >>= 1) {
        if (t < o) sd[t] += sd[t + o];
        __syncthreads();
    }
    if (t == 0) blk[blockIdx.x] = sd[0];
}
__global__ void scan_single_block(int* blk, int nb)
{
    __shared__ int tmp[1024];
    int t = threadIdx.x;
    int v = (t < nb) ? blk[t] : 0;
    tmp[t] = v;
    __syncthreads();
    for (int o = 1; o < 1024; o <<= 1) {
        int u = (t >= o) ? tmp[t - o] : 0;
        __syncthreads();
        tmp[t] += u;
        __syncthreads();
    }
    if (t < nb) blk[t] = tmp[t] - v;
}
__global__ void scan_final(const int* __restrict__ deg, const int* __restrict__ blk,
                           int* __restrict__ rowptr, int* __restrict__ cursor, int n, int E)
{
    __shared__ int tmp[256];
    int t = threadIdx.x;
    int i = blockIdx.x * 256 + t;
    int v = (i < n) ? deg[i] : 0;
    tmp[t] = v;
    __syncthreads();
    for (int o = 1; o < 256; o <<= 1) {
        int u = (t >= o) ? tmp[t - o] : 0;
        __syncthreads();
        tmp[t] += u;
        __syncthreads();
    }
    int excl = tmp[t] - v + blk[blockIdx.x];
    if (i < n) { rowptr[i] = excl; cursor[i] = excl; }
    if (blockIdx.x == 0 && t == 0) rowptr[n] = E;
}
__global__ void fill_csr_kernel(const int* __restrict__ dst, int* __restrict__ cursor,
                                int* __restrict__ eidx, int E)
{
    int e = blockIdx.x * 256 + threadIdx.x;
    if (e < E) {
        int p = atomicAdd(&cursor[dst[e]], 1);
        eidx[p] = e;
    }
}

// ======================= mma.sync 2-term fp16 GEMM =======================
// C[M,N] = A[M,K] @ W[K,N]; A fp16 [M,K] row-major, W transposed split fp16
// (Bhi,Blo) [N,K] row-major.  C = A*Bhi + A*Blo (fp32 acc).
// CTA 128x128, 8 warps of 64x32, BK=32, 3 stages, 2 CTAs/SM.
// Grid: blockIdx.x = n-tile (fast) -> consecutive CTAs share the A m-tile.
// flags: 1=bias, 2=relu, 4=residual(fp32 [M,N]), 8=fp16 out (else fp32 out)
#define RB 80
#define TILE_B (128 * RB)
#define SO_A   0
#define SO_BHI (1 * TILE_B)
#define SO_BLO (2 * TILE_B)
#define STAGE_B (3 * TILE_B)
#define GEMM_SMEM (3 * STAGE_B)

__device__ __forceinline__ void load_stage(uint32_t sbase,
    const __half* __restrict__ A, const __half* __restrict__ B_hi,
    const __half* __restrict__ B_lo,
    int K, int m0, int n0, int k0, int tid)
{
#pragma unroll
    for (int i = 0; i < 2; i++) {
        int g = tid + i * 256;
        int row = g >> 2, ch = g & 3;
        uint32_t so = (uint32_t)row * RB + (uint32_t)ch * 16;
        size_t ao = (size_t)(m0 + row) * K + k0 + ch * 8;
        size_t bo = (size_t)(n0 + row) * K + k0 + ch * 8;
        CP16(sbase + SO_A + so, A + ao);
        CP16(sbase + SO_BHI + so, B_hi + bo);
        CP16(sbase + SO_BLO + so, B_lo + bo);
    }
}

__global__ __launch_bounds__(256, 2) void mma_gemm_kernel(
    const __half* __restrict__ A,
    const __half* __restrict__ Bhi, const __half* __restrict__ Blo,
    const float* __restrict__ bias, const float* __restrict__ res,
    float* __restrict__ Cf, __half* __restrict__ Ch,
    int M, int N, int K, int flags)
{
    extern __shared__ __align__(128) char smem[];
    uint32_t sb = smem_u32(smem);
    int tid = threadIdx.x;
    int wid = tid >> 5, lane = tid & 31;
    int m0 = blockIdx.y * 128, n0 = blockIdx.x * 128;
    int nk = K >> 5;

    load_stage(sb, A, Bhi, Blo, K, m0, n0, 0, tid);
    CP_COMMIT();
    load_stage(sb + STAGE_B, A, Bhi, Blo, K, m0, n0, 32, tid);
    CP_COMMIT();

    float acc[4][4][4];
#pragma unroll
    for (int i = 0; i < 4; i++)
#pragma unroll
        for (int j = 0; j < 4; j++)
#pragma unroll
            for (int q = 0; q < 4; q++) acc[i][j][q] = 0.f;

    int mo = (wid & 1) * 64, no = (wid >> 1) * 32;
    int a_row = mo + (lane & 15);
    int a_k8  = lane >> 4;
    int b_row = ((lane >> 4) << 3) + (lane & 7);
    int b_k8  = (lane >> 3) & 1;

    for (int k = 0; k < nk; k++) {
        if (k == nk - 1) { CP_WAIT0(); } else { CP_WAIT1(); }
        __syncthreads();
        uint32_t base = sb + (uint32_t)(k % 3) * STAGE_B;
        if (k + 2 < nk)
            load_stage(sb + (uint32_t)((k + 2) % 3) * STAGE_B, A, Bhi, Blo,
                       K, m0, n0, (k + 2) * 32, tid);
        CP_COMMIT();
#pragma unroll
        for (int k16 = 0; k16 < 2; k16++) {
            int kk8 = k16 * 2;
            uint32_t ah[4][4];
#pragma unroll
            for (int i = 0; i < 4; i++) {
                uint32_t aaddr = base + SO_A + (uint32_t)(a_row + i * 16) * RB
                               + (uint32_t)(kk8 + a_k8) * 16;
                ldm4(ah[i], aaddr);
            }
#pragma unroll
            for (int j = 0; j < 2; j++) {
                uint32_t bh[4], bl[4];
                uint32_t baddr = base + SO_BHI + (uint32_t)(no + j * 16 + b_row) * RB
                               + (uint32_t)(kk8 + b_k8) * 16;
                ldm4(bh, baddr);
                ldm4(bl, baddr + (SO_BLO - SO_BHI));
#pragma unroll
                for (int i = 0; i < 4; i++) {
                    mma_f16(acc[i][2 * j],     ah[i], &bh[0]);
                    mma_f16(acc[i][2 * j + 1], ah[i], &bh[2]);
                    mma_f16(acc[i][2 * j],     ah[i], &bl[0]);
                    mma_f16(acc[i][2 * j + 1], ah[i], &bl[2]);
                }
            }
        }
    }

    // epilogue
#pragma unroll
    for (int i = 0; i < 4; i++) {
        int r0 = m0 + mo + i * 16 + (lane >> 2);
#pragma unroll
        for (int half = 0; half < 2; half++) {
            int r = r0 + half * 8;
            if (r >= M) continue;
#pragma unroll
            for (int nb = 0; nb < 4; nb++) {
                int col = n0 + no + nb * 8 + 2 * (lane & 3);
                float v0 = acc[i][nb][half * 2 + 0];
                float v1 = acc[i][nb][half * 2 + 1];
                if (flags & 1) { v0 += bias[col]; v1 += bias[col + 1]; }
                if (flags & 4) {
                    float2 t = *(const float2*)(res + (size_t)r * N + col);
                    v0 += t.x; v1 += t.y;
                }
                if (flags & 2) { v0 = fmaxf(v0, 0.f); v1 = fmaxf(v1, 0.f); }
                if (flags & 8) {
                    *(__half2*)(Ch + (size_t)r * N + col) =
                        __halves2half2(__float2half(v0), __float2half(v1));
                } else {
                    *(float2*)(Cf + (size_t)r * N + col) = make_float2(v0, v1);
                }
            }
        }
    }
}

// ---------------- weight transpose+split (fp16 hi/lo) --------------------------
__global__ void tsplit_kernel(const float* __restrict__ W,
                              __half* __restrict__ thi, __half* __restrict__ tlo,
                              int K, int N)
{
    int idx = blockIdx.x * 256 + threadIdx.x;
    if (idx >= K * N) return;
    int k = idx / N, n = idx % N;
    float w = W[idx];
    __half hi = __float2half(w);
    __half lo = __float2half(w - __half2float(hi));
    thi[(size_t)n * K + k] = hi;
    tlo[(size_t)n * K + k] = lo;
}

// ---------------- node encoder (fp16 out) --------------------------------------
__global__ void enc_kernel(const float* __restrict__ xg, const float* __restrict__ W,
                           const float* __restrict__ b, __half* __restrict__ out)
{
    __shared__ float sx[16];
    int n = blockIdx.x, c = threadIdx.x;
    if (c < 16) sx[c] = xg[(size_t)n * 16 + c];
    __syncthreads();
    float v = b[c];
#pragma unroll
    for (int k = 0; k < 16; k++) v = fmaf(sx[k], W[k * H + c], v);
    out[(size_t)n * H + c] = __float2half(v);
}

// ---------------- tiny [E,4]@[4,4]+b projection --------------------------------
__global__ void basis4_kernel(const float* __restrict__ in, const float* __restrict__ W,
                              const float* __restrict__ b, float* __restrict__ out, int E)
{
    int e = blockIdx.x * blockDim.x + threadIdx.x;
    if (e >= E) return;
    float4 x = *(const float4*)(in + (size_t)e * 4);
    float o0 = b[0] + x.x * W[0] + x.y * W[4] + x.z * W[8]  + x.w * W[12];
    float o1 = b[1] + x.x * W[1] + x.y * W[5] + x.z * W[9]  + x.w * W[13];
    float o2 = b[2] + x.x * W[2] + x.y * W[6] + x.z * W[10] + x.w * W[14];
    float o3 = b[3] + x.x * W[3] + x.y * W[7] + x.z * W[11] + x.w * W[15];
    *(float4*)(out + (size_t)e * 4) = make_float4(o0, o1, o2, o3);
}

// ---------------- fused first-message ------------------------------------------
#define MEPB 16
__global__ __launch_bounds__(256) void msg_edge_kernel(
    const float* __restrict__ AB,
    const float* __restrict__ ea, const float* __restrict__ xlg,
    const float* __restrict__ Wc, const float* __restrict__ Wd,
    const float* __restrict__ bmsg,
    const int* __restrict__ srcg, const int* __restrict__ dstg,
    float* __restrict__ h, int Eg)
{
    __shared__ float sWc[16 * H];
    __shared__ float sWd[4 * H];
    __shared__ float sb[H];
    __shared__ float sea[MEPB][16];
    __shared__ float sxl[MEPB][4];
    int tid = threadIdx.x;
    for (int i = tid; i < 16 * H; i += 256) sWc[i] = Wc[i];
    for (int i = tid; i < 4 * H; i += 256) sWd[i] = Wd[i];
    sb[tid] = bmsg[tid];
    int e0 = blockIdx.x * MEPB;
    for (int i = tid; i < MEPB * 16; i += 256) {
        int e = e0 + i / 16;
        if (e < Eg) sea[i / 16][i % 16] = ea[(size_t)e * 16 + (i % 16)];
    }
    for (int i = tid; i < MEPB * 4; i += 256) {
        int e = e0 + i / 4;
        if (e < Eg) sxl[i / 4][i % 4] = xlg[(size_t)e * 4 + (i % 4)];
    }
    __syncthreads();
    int c = tid;
    for (int i = 0; i < MEPB; i++) {
        int e = e0 + i;
        if (e >= Eg) break;
        int s = srcg[e], d = dstg[e];
        float v = AB[(size_t)s * 512 + c] + AB[(size_t)d * 512 + 256 + c] + sb[c];
#pragma unroll
        for (int k = 0; k < 16; k++) v = fmaf(sea[i][k], sWc[k * H + c], v);
#pragma unroll
        for (int k = 0; k < 4; k++) v = fmaf(sxl[i][k], sWd[k * H + c], v);
        h[(size_t)e * H + c] = v;
    }
}

// ---------------- BN coefficient computation -----------------------------------
__global__ void bn_coef_kernel(const double* __restrict__ acc,
                               const float* __restrict__ gamma, const float* __restrict__ beta,
                               float* __restrict__ scale, float* __restrict__ shift, int M)
{
    int c = threadIdx.x;
    double mu = acc[c] / (double)M;
    double var = acc[H + c] / (double)M - mu * mu;
    float inv = rsqrtf((float)var + 1e-5f);
    float sc = gamma[c] * inv;
    scale[c] = sc;
    shift[c] = beta[c] - (float)mu * sc;
}

// ---------------- fused GENConv aggregation (CSR gather, fp16 out) -------------
// Reference-shift softmax: first edge's weight is exactly 1 (no exp);
// remaining edges use fast __expf of the (shift-invariant) difference.
#define RPB 8
__global__ __launch_bounds__(256) void gen_aggr_kernel(
    const float* __restrict__ x, const float* __restrict__ nbg, const float* __restrict__ ebg,
    const float* __restrict__ Wnb, const float* __restrict__ bnb,
    const float* __restrict__ Web, const float* __restrict__ beb,
    const float* __restrict__ bnscale, const float* __restrict__ bnshift,
    const int* __restrict__ src, const int* __restrict__ rowptr, const int* __restrict__ eidx,
    __half* __restrict__ aout, int E, int use_bn)
{
    __shared__ float sWn[4 * H], sWe[4 * H], sbn[H], sbe[H];
    int tid = threadIdx.x;
    for (int i = tid; i < 4 * H; i += 256) { sWn[i] = Wnb[i]; sWe[i] = Web[i]; }
    sbn[tid] = bnb[tid];
    sbe[tid] = beb[tid];
    __syncthreads();
    int c = tid;
    float sc = 1.f, sh = 0.f;
    if (use_bn) { sc = bnscale[c]; sh = bnshift[c]; }
    int d0 = blockIdx.x * RPB;
#pragma unroll
    for (int rr = 0; rr < RPB; rr++) {
        int d = d0 + rr;
        if (d >= E) break;
        int beg = rowptr[d], end = rowptr[d + 1];
        float se = 0.f, sw = 0.f, m0 = 0.f;
        for (int p = beg; p < end; p++) {
            int e = eidx[p];
            int s = src[e];
            float4 nv = *(const float4*)(nbg + (size_t)s * 4);
            float4 ev4 = *(const float4*)(ebg + (size_t)e * 4);
            float nbv = sbn[c];
            nbv = fmaf(nv.x, sWn[c], nbv);
            nbv = fmaf(nv.y, sWn[H + c], nbv);
            nbv = fmaf(nv.z, sWn[2 * H + c], nbv);
            nbv = fmaf(nv.w, sWn[3 * H + c], nbv);
            float ebv = sbe[c];
            ebv = fmaf(ev4.x, sWe[c], ebv);
            ebv = fmaf(ev4.y, sWe[H + c], ebv);
            ebv = fmaf(ev4.z, sWe[2 * H + c], ebv);
            ebv = fmaf(ev4.w, sWe[3 * H + c], ebv);
            float xv = x[(size_t)s * H + c];
            if (use_bn) xv = fmaxf(fmaf(xv, sc, sh), 0.f);
            float mv = fmaxf(xv + nbv + ebv, 0.f) + 1e-7f;
            if (p == beg) {
                m0 = mv;
                se = 1.f;
                sw = mv;
            } else {
                float dmv = fminf(fmaxf(mv - m0, -80.f), 80.f);
                float ee = __expf(dmv);
                se += ee;
                sw = fmaf(ee, mv, sw);
            }
        }
        float xv = x[(size_t)d * H + c];
        if (use_bn) xv = fmaxf(fmaf(xv, sc, sh), 0.f);
        float v = xv + __fdividef(sw, se + 1e-16f);
        aout[(size_t)d * H + c] = __float2half(v);
    }
}

// ---------------- BatchNorm statistics -----------------------------------------
__global__ void bn_stats_kernel(const float* __restrict__ h, int M, double* __restrict__ acc)
{
    int c = threadIdx.x;
    float s = 0.f, s2 = 0.f;
    for (int r = blockIdx.x; r < M; r += gridDim.x) {
        float v = h[(size_t)r * H + c];
        s += v;
        s2 = fmaf(v, v, s2);
    }
    atomicAdd(&acc[c], (double)s);
    atomicAdd(&acc[H + c], (double)s2);
}

// ---------------- node gather (BN fused, CSR over dst_g) -----------------------
__global__ void node_gather_kernel(const float* __restrict__ h,
                                   const float* __restrict__ bnscale,
                                   const float* __restrict__ bnshift,
                                   const int* __restrict__ rowptr, const int* __restrict__ eidx,
                                   float* __restrict__ node_emb)
{
    int n = blockIdx.x, c = threadIdx.x;
    float sc = bnscale[c], sh = bnshift[c];
    int beg = rowptr[n], end = rowptr[n + 1];
    float acc = 0.f;
    for (int p = beg; p < end; p++) {
        int e = eidx[p];
        acc += fmaf(h[(size_t)e * H + c], sc, sh);
    }
    node_emb[(size_t)n * H + c] = acc;
}

__global__ void pool_kernel(const float* __restrict__ node_emb, const int* __restrict__ batch,
                            float* __restrict__ gsum, float* __restrict__ cnt)
{
    int n = blockIdx.x;
    int c = threadIdx.x;
    int b = batch[n];
    atomicAdd(gsum + (size_t)b * H + c, node_emb[(size_t)n * H + c]);
    if (c == 0) atomicAdd(&cnt[b], 1.0f);
}

__global__ void predict_kernel(const float* __restrict__ gsum, const float* __restrict__ cnt,
                               const float* __restrict__ Wp, const float* __restrict__ bp,
                               float* __restrict__ out)
{
    int g = blockIdx.x, c = threadIdx.x;
    float v = gsum[(size_t)g * H + c] * Wp[c];
    __shared__ float red[8];
#pragma unroll
    for (int o = 16; o > 0; o >>= 1) v += __shfl_down_sync(0xffffffffu, v, o);
    if ((c & 31) == 0) red[c >> 5] = v;
    __syncthreads();
    if (c == 0) {
        float t = 0.f;
#pragma unroll
        for (int i = 0; i < 8; i++) t += red[i];
        out[g] = t / fmaxf(cnt[g], 1.0f) + bp[0];
    }
}

// -------------------------------------------------------------------------------
static void* symA(const void* sym)
{
    void* p = nullptr;
    cudaGetSymbolAddress(&p, sym);
    return p;
}

static void build_csr(const int* dst, int n, int E, int* deg, int* blk,
                      int* rowptr, int* cursor, int* eidx)
{
    int nb = (n + 255) / 256;
    zero_int_kernel<<<nb, 256>>>(deg, n);
    hist_kernel<<<(E + 255) / 256, 256>>>(dst, deg, E);
    scan_block_sums<<<nb, 256>>>(deg, blk, n);
    scan_single_block<<<1, 1024>>>(blk, nb);
    scan_final<<<nb, 256>>>(deg, blk, rowptr, cursor, n, E);
    fill_csr_kernel<<<(E + 255) / 256, 256>>>(dst, cursor, eidx, E);
}

extern "C" void kernel_launch(void* const* d_in, const int* in_sizes, int n_in,
                              void* d_out, int out_size)
{
    const float* x_g       = (const float*)d_in[0];
    const float* ea_g      = (const float*)d_in[1];
    const float* x_lg      = (const float*)d_in[2];
    const float* edb       = (const float*)d_in[3];
    const float* ea_lg     = (const float*)d_in[4];
    const float* W_enc     = (const float*)d_in[5];
    const float* b_enc     = (const float*)d_in[6];
    const float* W_msg     = (const float*)d_in[7];
    const float* b_msg     = (const float*)d_in[8];
    const float* Wg_nb     = (const float*)d_in[9];
    const float* bg_nb     = (const float*)d_in[10];
    const float* Wg_eb     = (const float*)d_in[11];
    const float* bg_eb     = (const float*)d_in[12];
    const float* Wl_nb     = (const float*)d_in[13];
    const float* bl_nb     = (const float*)d_in[14];
    const float* Wl_eb     = (const float*)d_in[15];
    const float* bl_eb     = (const float*)d_in[16];
    const float* W1        = (const float*)d_in[17];
    const float* b1        = (const float*)d_in[18];
    const float* W2        = (const float*)d_in[19];
    const float* b2        = (const float*)d_in[20];
    const float* bn_gamma  = (const float*)d_in[21];
    const float* bn_beta   = (const float*)d_in[22];
    const float* W_pred    = (const float*)d_in[23];
    const float* b_pred    = (const float*)d_in[24];
    const int*   eig       = (const int*)d_in[25];
    const int*   eil       = (const int*)d_in[26];
    const int*   batch     = (const int*)d_in[27];

    int N   = in_sizes[0] / 16;   // 20000
    int Eg  = in_sizes[1] / 16;   // 200000
    int Elg = in_sizes[4] / 4;    // 400000
    const int L = 4;

    cudaFuncSetAttribute(mma_gemm_kernel, cudaFuncAttributeMaxDynamicSharedMemorySize,
                         GEMM_SMEM);

    float* p_AB   = (float*)symA(g_AB);
    float* p_h    = (float*)symA(g_h);
    float* p_nbg  = (float*)symA(g_nbg);
    float* p_ebg  = (float*)symA(g_ebg);
    float* p_ne   = (float*)symA(g_nodeemb);
    double* p_bnacc = (double*)symA(g_bnacc);
    float* p_bnsc = (float*)symA(g_bnscale);
    float* p_bnsh = (float*)symA(g_bnshift);
    float* p_gsum = (float*)symA(g_gsum);
    float* p_cnt  = (float*)symA(g_cnt);

    int* p_deg    = (int*)symA(g_deg);
    int* p_cursor = (int*)symA(g_cursor);
    int* p_blk    = (int*)symA(g_blk);
    int* p_rp_lg  = (int*)symA(g_rowptr_lg);
    int* p_ei_lg  = (int*)symA(g_eidx_lg);
    int* p_rp_g   = (int*)symA(g_rowptr_g);
    int* p_ei_g   = (int*)symA(g_eidx_g);

    __half* p_node = (__half*)symA(g_node);
    __half* p_act  = (__half*)symA(g_act);
    __half* p_hid  = (__half*)symA(g_hid);
    __half* p_wthi = (__half*)symA(g_wthi);
    __half* p_wtlo = (__half*)symA(g_wtlo);

    const int* src_g = eig;
    const int* dst_g = eig + Eg;
    const int* src_l = eil;
    const int* dst_l = eil + Elg;

    int mtE = (Eg + 127) / 128;   // 1563
    int mtN = (N + 127) / 128;    // 157

    // --- CSR builds ---
    build_csr(dst_l, Eg, Elg, p_deg, p_blk, p_rp_lg, p_cursor, p_ei_lg);
    build_csr(dst_g, N, Eg, p_deg, p_blk, p_rp_g, p_cursor, p_ei_g);

    // --- weight transpose + split ---
    tsplit_kernel<<<(65536 + 255) / 256, 256>>>(W_msg,           p_wthi + OFF_WMSG,         p_wtlo + OFF_WMSG,         256, 256);
    tsplit_kernel<<<(65536 + 255) / 256, 256>>>(W_msg + 256 * H, p_wthi + OFF_WMSG + 65536, p_wtlo + OFF_WMSG + 65536, 256, 256);
    for (int l = 0; l < L; l++) {
        tsplit_kernel<<<(131072 + 255) / 256, 256>>>(
            W1 + (size_t)l * 131072, p_wthi + OFF_W1T + l * 131072, p_wtlo + OFF_W1T + l * 131072, 256, 512);
        tsplit_kernel<<<(131072 + 255) / 256, 256>>>(
            W2 + (size_t)l * 131072, p_wthi + OFF_W2T + l * 131072, p_wtlo + OFF_W2T + l * 131072, 512, 256);
    }

    // --- node encoder + combined msg GEMM (N=512) ---
    enc_kernel<<<N, 256>>>(x_g, W_enc, b_enc, p_node);
    {
        dim3 grid(4, mtN);   // n fast
        mma_gemm_kernel<<<grid, 256, GEMM_SMEM>>>(
            p_node, p_wthi + OFF_WMSG, p_wtlo + OFF_WMSG,
            nullptr, nullptr, p_AB, nullptr, N, 512, 256, 0);
    }
    basis4_kernel<<<(Eg + 255) / 256, 256>>>(edb,   Wg_nb, bg_nb, p_nbg, Eg);
    basis4_kernel<<<(Elg + 255) / 256, 256>>>(ea_lg, Wg_eb, bg_eb, p_ebg, Elg);
    msg_edge_kernel<<<(Eg + MEPB - 1) / MEPB, 256>>>(
        p_AB, ea_g, x_lg, W_msg + 512 * H, W_msg + 528 * H, b_msg,
        src_g, dst_g, p_h, Eg);

    // --- 4 GENConv layers ---
    for (int l = 0; l < L; l++) {
        int use_bn = (l > 0) ? 1 : 0;
        if (use_bn) {
            cudaMemsetAsync(p_bnacc, 0, 2 * H * sizeof(double));
            bn_stats_kernel<<<1024, 256>>>(p_h, Eg, p_bnacc);
            bn_coef_kernel<<<1, 256>>>(p_bnacc, bn_gamma + (l - 1) * H, bn_beta + (l - 1) * H,
                                       p_bnsc, p_bnsh, Eg);
        }
        gen_aggr_kernel<<<(Eg + RPB - 1) / RPB, 256>>>(
            p_h, p_nbg, p_ebg,
            Wl_nb + l * 4 * H, bl_nb + l * H,
            Wl_eb + l * 4 * H, bl_eb + l * H,
            p_bnsc, p_bnsh, src_l, p_rp_lg, p_ei_lg,
            p_act, Eg, use_bn);

        // GEMM1: hid = relu(act @ W1 + b1), fp16 out
        {
            dim3 grid(4, mtE);   // n fast
            mma_gemm_kernel<<<grid, 256, GEMM_SMEM>>>(
                p_act, p_wthi + OFF_W1T + l * 131072, p_wtlo + OFF_W1T + l * 131072,
                b1 + l * 512, nullptr, nullptr, p_hid,
                Eg, 512, 256, 1 | 2 | 8);
        }
        // GEMM2: h = hid @ W2 + b2 (+ residual for l>0), fp32 out
        {
            dim3 grid(2, mtE);   // n fast
            mma_gemm_kernel<<<grid, 256, GEMM_SMEM>>>(
                p_hid, p_wthi + OFF_W2T + l * 131072, p_wtlo + OFF_W2T + l * 131072,
                b2 + l * 256, (l > 0) ? p_h : nullptr, p_h, nullptr,
                Eg, 256, 512, (l > 0) ? (1 | 4) : 1);
        }
    }

    // --- final BN coefs + CSR node gather ---
    cudaMemsetAsync(p_bnacc, 0, 2 * H * sizeof(double));
    bn_stats_kernel<<<1024, 256>>>(p_h, Eg, p_bnacc);
    bn_coef_kernel<<<1, 256>>>(p_bnacc, bn_gamma + 3 * H, bn_beta + 3 * H, p_bnsc, p_bnsh, Eg);

    node_gather_kernel<<<N, 256>>>(p_h, p_bnsc, p_bnsh, p_rp_g, p_ei_g, p_ne);

    cudaMemsetAsync(p_gsum, 0, NGRAPH * H * sizeof(float));
    cudaMemsetAsync(p_cnt,  0, NGRAPH * sizeof(float));
    pool_kernel<<<N, 256>>>(p_ne, batch, p_gsum, p_cnt);
    predict_kernel<<<NGRAPH, 256>>>(p_gsum, p_cnt, W_pred, b_pred, (float*)d_out);
}

// round 12
// speedup vs baseline: 1.5026x; 1.0753x over previous
#include <cuda_runtime.h>
#include <cuda_fp16.h>
#include <cstdint>

#define H 256
#define NGRAPH 128
#define MAXN   20224
#define MAXEG  200192
#define MAXELG 400128

// ---------------- scratch ----------------
__device__ float g_AB[(size_t)MAXN * 512];
__device__ float g_h[(size_t)MAXEG * H];
__device__ float g_nbg[(size_t)MAXEG * 4];
__device__ float g_ebg[(size_t)MAXELG * 4];
__device__ float g_bnacc[2 * H];
__device__ float g_bnscale[H];
__device__ float g_bnshift[H];
__device__ float g_gsum[NGRAPH * H];
__device__ float g_cnt[NGRAPH];

// CSR scratch
__device__ int g_deg[MAXEG];
__device__ int g_cursor[MAXEG];
__device__ int g_blk[1024];
__device__ int g_rowptr_lg[MAXEG + 1];
__device__ int g_eidx_lg[MAXELG];
__device__ int g_rowptr_g[MAXN + 1];
__device__ int g_eidx_g[MAXEG];

// fp16 activation buffers (pad rows never written -> stay zero)
__device__ __half g_node[(size_t)MAXN * H];
__device__ __half g_act[(size_t)MAXEG * H];
__device__ __half g_hid[(size_t)MAXEG * 2 * H];

// transposed/split fp16 weights arena
#define OFF_WMSG 0
#define OFF_W1T  (512 * 256)
#define OFF_W2T  (OFF_W1T + 4 * 131072)
#define WT_TOTAL (OFF_W2T + 4 * 131072)
__device__ __half g_wthi[WT_TOTAL];
__device__ __half g_wtlo[WT_TOTAL];

// ======================= helpers =======================
__device__ __forceinline__ uint32_t smem_u32(const void* p) {
    uint32_t a;
    asm("{ .reg .u64 t; cvta.to.shared.u64 t, %1; cvt.u32.u64 %0, t; }" : "=r"(a) : "l"(p));
    return a;
}
#define CP16(dst, src) \
    asm volatile("cp.async.cg.shared.global [%0], [%1], 16;" :: "r"(dst), "l"(src) : "memory")
#define CP_COMMIT() asm volatile("cp.async.commit_group;" ::: "memory")
#define CP_WAIT1()  asm volatile("cp.async.wait_group 1;" ::: "memory")
#define CP_WAIT0()  asm volatile("cp.async.wait_group 0;" ::: "memory")

__device__ __forceinline__ void ldm4(uint32_t (&r)[4], uint32_t addr) {
    asm volatile("ldmatrix.sync.aligned.m8n8.x4.shared.b16 {%0,%1,%2,%3}, [%4];"
                 : "=r"(r[0]), "=r"(r[1]), "=r"(r[2]), "=r"(r[3]) : "r"(addr));
}
__device__ __forceinline__ void mma_f16(float (&d)[4], const uint32_t (&a)[4], const uint32_t* b) {
    asm volatile(
        "mma.sync.aligned.m16n8k16.row.col.f32.f16.f16.f32 "
        "{%0,%1,%2,%3}, {%4,%5,%6,%7}, {%8,%9}, {%0,%1,%2,%3};"
        : "+f"(d[0]), "+f"(d[1]), "+f"(d[2]), "+f"(d[3])
        : "r"(a[0]), "r"(a[1]), "r"(a[2]), "r"(a[3]), "r"(b[0]), "r"(b[1]));
}

// ======================= CSR build kernels =======================
__global__ void zero_int_kernel(int* a, int n)
{
    int i = blockIdx.x * 256 + threadIdx.x;
    if (i < n) a[i] = 0;
}
__global__ void hist_kernel(const int* __restrict__ dst, int* __restrict__ deg, int E)
{
    int i = blockIdx.x * 256 + threadIdx.x;
    if (i < E) atomicAdd(&deg[dst[i]], 1);
}
__global__ void scan_block_sums(const int* __restrict__ deg, int* __restrict__ blk, int n)
{
    __shared__ int sd[256];
    int t = threadIdx.x;
    int i = blockIdx.x * 256 + t;
    sd[t] = (i < n) ? deg[i] : 0;
    __syncthreads();
    for (int o = 128; o > 0; o >>= 1) {
        if (t < o) sd[t] += sd[t + o];
        __syncthreads();
    }
    if (t == 0) blk[blockIdx.x] = sd[0];
}
__global__ void scan_single_block(int* blk, int nb)
{
    __shared__ int tmp[1024];
    int t = threadIdx.x;
    int v = (t < nb) ? blk[t] : 0;
    tmp[t] = v;
    __syncthreads();
    for (int o = 1; o < 1024; o <<= 1) {
        int u = (t >= o) ? tmp[t - o] : 0;
        __syncthreads();
        tmp[t] += u;
        __syncthreads();
    }
    if (t < nb) blk[t] = tmp[t] - v;
}
__global__ void scan_final(const int* __restrict__ deg, const int* __restrict__ blk,
                           int* __restrict__ rowptr, int* __restrict__ cursor, int n, int E)
{
    __shared__ int tmp[256];
    int t = threadIdx.x;
    int i = blockIdx.x * 256 + t;
    int v = (i < n) ? deg[i] : 0;
    tmp[t] = v;
    __syncthreads();
    for (int o = 1; o < 256; o <<= 1) {
        int u = (t >= o) ? tmp[t - o] : 0;
        __syncthreads();
        tmp[t] += u;
        __syncthreads();
    }
    int excl = tmp[t] - v + blk[blockIdx.x];
    if (i < n) { rowptr[i] = excl; cursor[i] = excl; }
    if (blockIdx.x == 0 && t == 0) rowptr[n] = E;
}
__global__ void fill_csr_kernel(const int* __restrict__ dst, int* __restrict__ cursor,
                                int* __restrict__ eidx, int E)
{
    int e = blockIdx.x * 256 + threadIdx.x;
    if (e < E) {
        int p = atomicAdd(&cursor[dst[e]], 1);
        eidx[p] = e;
    }
}

// ======================= mma.sync 2-term fp16 GEMM =======================
// C[M,N] = A[M,K] @ W[K,N]; A fp16 [M,K] row-major, W transposed split fp16
// (Bhi,Blo) [N,K] row-major.  C = A*Bhi + A*Blo (fp32 acc).
// CTA 128x128, 8 warps of 64x32, BK=32, 3 stages, 2 CTAs/SM. n-tile fast in grid.
// flags: 1=bias, 2=relu, 4=residual fp32, 8=fp16 out, 32=BN stats (float bnacc[2N])
#define RB 80
#define TILE_B (128 * RB)
#define SO_A   0
#define SO_BHI (1 * TILE_B)
#define SO_BLO (2 * TILE_B)
#define STAGE_B (3 * TILE_B)
#define GEMM_SMEM (3 * STAGE_B)

__device__ __forceinline__ void load_stage(uint32_t sbase,
    const __half* __restrict__ A, const __half* __restrict__ B_hi,
    const __half* __restrict__ B_lo,
    int K, int m0, int n0, int k0, int tid)
{
#pragma unroll
    for (int i = 0; i < 2; i++) {
        int g = tid + i * 256;
        int row = g >> 2, ch = g & 3;
        uint32_t so = (uint32_t)row * RB + (uint32_t)ch * 16;
        size_t ao = (size_t)(m0 + row) * K + k0 + ch * 8;
        size_t bo = (size_t)(n0 + row) * K + k0 + ch * 8;
        CP16(sbase + SO_A + so, A + ao);
        CP16(sbase + SO_BHI + so, B_hi + bo);
        CP16(sbase + SO_BLO + so, B_lo + bo);
    }
}

__global__ __launch_bounds__(256, 2) void mma_gemm_kernel(
    const __half* __restrict__ A,
    const __half* __restrict__ Bhi, const __half* __restrict__ Blo,
    const float* __restrict__ bias, const float* __restrict__ res,
    float* __restrict__ Cf, __half* __restrict__ Ch, float* __restrict__ bnacc,
    int M, int N, int K, int flags)
{
    extern __shared__ __align__(128) char smem[];
    uint32_t sb = smem_u32(smem);
    int tid = threadIdx.x;
    int wid = tid >> 5, lane = tid & 31;
    int m0 = blockIdx.y * 128, n0 = blockIdx.x * 128;
    int nk = K >> 5;

    load_stage(sb, A, Bhi, Blo, K, m0, n0, 0, tid);
    CP_COMMIT();
    load_stage(sb + STAGE_B, A, Bhi, Blo, K, m0, n0, 32, tid);
    CP_COMMIT();

    float acc[4][4][4];
#pragma unroll
    for (int i = 0; i < 4; i++)
#pragma unroll
        for (int j = 0; j < 4; j++)
#pragma unroll
            for (int q = 0; q < 4; q++) acc[i][j][q] = 0.f;

    int mo = (wid & 1) * 64, no = (wid >> 1) * 32;
    int a_row = mo + (lane & 15);
    int a_k8  = lane >> 4;
    int b_row = ((lane >> 4) << 3) + (lane & 7);
    int b_k8  = (lane >> 3) & 1;

    for (int k = 0; k < nk; k++) {
        if (k == nk - 1) { CP_WAIT0(); } else { CP_WAIT1(); }
        __syncthreads();
        uint32_t base = sb + (uint32_t)(k % 3) * STAGE_B;
        if (k + 2 < nk)
            load_stage(sb + (uint32_t)((k + 2) % 3) * STAGE_B, A, Bhi, Blo,
                       K, m0, n0, (k + 2) * 32, tid);
        CP_COMMIT();
#pragma unroll
        for (int k16 = 0; k16 < 2; k16++) {
            int kk8 = k16 * 2;
            uint32_t ah[4][4];
#pragma unroll
            for (int i = 0; i < 4; i++) {
                uint32_t aaddr = base + SO_A + (uint32_t)(a_row + i * 16) * RB
                               + (uint32_t)(kk8 + a_k8) * 16;
                ldm4(ah[i], aaddr);
            }
#pragma unroll
            for (int j = 0; j < 2; j++) {
                uint32_t bh[4], bl[4];
                uint32_t baddr = base + SO_BHI + (uint32_t)(no + j * 16 + b_row) * RB
                               + (uint32_t)(kk8 + b_k8) * 16;
                ldm4(bh, baddr);
                ldm4(bl, baddr + (SO_BLO - SO_BHI));
#pragma unroll
                for (int i = 0; i < 4; i++) {
                    mma_f16(acc[i][2 * j],     ah[i], &bh[0]);
                    mma_f16(acc[i][2 * j + 1], ah[i], &bh[2]);
                    mma_f16(acc[i][2 * j],     ah[i], &bl[0]);
                    mma_f16(acc[i][2 * j + 1], ah[i], &bl[2]);
                }
            }
        }
    }

    // epilogue (+ optional fused BN statistics)
    float st[4][2], sq[4][2];
#pragma unroll
    for (int nb = 0; nb < 4; nb++) {
        st[nb][0] = st[nb][1] = 0.f;
        sq[nb][0] = sq[nb][1] = 0.f;
    }
#pragma unroll
    for (int i = 0; i < 4; i++) {
        int r0 = m0 + mo + i * 16 + (lane >> 2);
#pragma unroll
        for (int half = 0; half < 2; half++) {
            int r = r0 + half * 8;
            if (r >= M) continue;
#pragma unroll
            for (int nb = 0; nb < 4; nb++) {
                int col = n0 + no + nb * 8 + 2 * (lane & 3);
                float v0 = acc[i][nb][half * 2 + 0];
                float v1 = acc[i][nb][half * 2 + 1];
                if (flags & 1) { v0 += bias[col]; v1 += bias[col + 1]; }
                if (flags & 4) {
                    float2 t = *(const float2*)(res + (size_t)r * N + col);
                    v0 += t.x; v1 += t.y;
                }
                if (flags & 2) { v0 = fmaxf(v0, 0.f); v1 = fmaxf(v1, 0.f); }
                if (flags & 32) {
                    st[nb][0] += v0; sq[nb][0] = fmaf(v0, v0, sq[nb][0]);
                    st[nb][1] += v1; sq[nb][1] = fmaf(v1, v1, sq[nb][1]);
                }
                if (flags & 8) {
                    *(__half2*)(Ch + (size_t)r * N + col) =
                        __halves2half2(__float2half(v0), __float2half(v1));
                } else {
                    *(float2*)(Cf + (size_t)r * N + col) = make_float2(v0, v1);
                }
            }
        }
    }
    if (flags & 32) {
#pragma unroll
        for (int nb = 0; nb < 4; nb++)
#pragma unroll
            for (int w = 0; w < 2; w++) {
                float s = st[nb][w], q = sq[nb][w];
                s += __shfl_xor_sync(0xffffffffu, s, 4);
                q += __shfl_xor_sync(0xffffffffu, q, 4);
                s += __shfl_xor_sync(0xffffffffu, s, 8);
                q += __shfl_xor_sync(0xffffffffu, q, 8);
                s += __shfl_xor_sync(0xffffffffu, s, 16);
                q += __shfl_xor_sync(0xffffffffu, q, 16);
                if ((lane >> 2) == 0) {
                    int col = n0 + no + nb * 8 + 2 * (lane & 3) + w;
                    atomicAdd(&bnacc[col], s);
                    atomicAdd(&bnacc[N + col], q);
                }
            }
    }
}

// ---------------- weight transpose+split (fp16 hi/lo) --------------------------
__global__ void tsplit_kernel(const float* __restrict__ W,
                              __half* __restrict__ thi, __half* __restrict__ tlo,
                              int K, int N)
{
    int idx = blockIdx.x * 256 + threadIdx.x;
    if (idx >= K * N) return;
    int k = idx / N, n = idx % N;
    float w = W[idx];
    __half hi = __float2half(w);
    __half lo = __float2half(w - __half2float(hi));
    thi[(size_t)n * K + k] = hi;
    tlo[(size_t)n * K + k] = lo;
}

// ---------------- node encoder (fp16 out) --------------------------------------
__global__ void enc_kernel(const float* __restrict__ xg, const float* __restrict__ W,
                           const float* __restrict__ b, __half* __restrict__ out)
{
    __shared__ float sx[16];
    int n = blockIdx.x, c = threadIdx.x;
    if (c < 16) sx[c] = xg[(size_t)n * 16 + c];
    __syncthreads();
    float v = b[c];
#pragma unroll
    for (int k = 0; k < 16; k++) v = fmaf(sx[k], W[k * H + c], v);
    out[(size_t)n * H + c] = __float2half(v);
}

// ---------------- tiny [E,4]@[4,4]+b projection --------------------------------
__global__ void basis4_kernel(const float* __restrict__ in, const float* __restrict__ W,
                              const float* __restrict__ b, float* __restrict__ out, int E)
{
    int e = blockIdx.x * blockDim.x + threadIdx.x;
    if (e >= E) return;
    float4 x = *(const float4*)(in + (size_t)e * 4);
    float o0 = b[0] + x.x * W[0] + x.y * W[4] + x.z * W[8]  + x.w * W[12];
    float o1 = b[1] + x.x * W[1] + x.y * W[5] + x.z * W[9]  + x.w * W[13];
    float o2 = b[2] + x.x * W[2] + x.y * W[6] + x.z * W[10] + x.w * W[14];
    float o3 = b[3] + x.x * W[3] + x.y * W[7] + x.z * W[11] + x.w * W[15];
    *(float4*)(out + (size_t)e * 4) = make_float4(o0, o1, o2, o3);
}

// ---------------- fused first-message ------------------------------------------
#define MEPB 16
__global__ __launch_bounds__(256) void msg_edge_kernel(
    const float* __restrict__ AB,
    const float* __restrict__ ea, const float* __restrict__ xlg,
    const float* __restrict__ Wc, const float* __restrict__ Wd,
    const float* __restrict__ bmsg,
    const int* __restrict__ srcg, const int* __restrict__ dstg,
    float* __restrict__ h, int Eg)
{
    __shared__ float sWc[16 * H];
    __shared__ float sWd[4 * H];
    __shared__ float sb[H];
    __shared__ float sea[MEPB][16];
    __shared__ float sxl[MEPB][4];
    int tid = threadIdx.x;
    for (int i = tid; i < 16 * H; i += 256) sWc[i] = Wc[i];
    for (int i = tid; i < 4 * H; i += 256) sWd[i] = Wd[i];
    sb[tid] = bmsg[tid];
    int e0 = blockIdx.x * MEPB;
    for (int i = tid; i < MEPB * 16; i += 256) {
        int e = e0 + i / 16;
        if (e < Eg) sea[i / 16][i % 16] = ea[(size_t)e * 16 + (i % 16)];
    }
    for (int i = tid; i < MEPB * 4; i += 256) {
        int e = e0 + i / 4;
        if (e < Eg) sxl[i / 4][i % 4] = xlg[(size_t)e * 4 + (i % 4)];
    }
    __syncthreads();
    int c = tid;
    for (int i = 0; i < MEPB; i++) {
        int e = e0 + i;
        if (e >= Eg) break;
        int s = srcg[e], d = dstg[e];
        float v = AB[(size_t)s * 512 + c] + AB[(size_t)d * 512 + 256 + c] + sb[c];
#pragma unroll
        for (int k = 0; k < 16; k++) v = fmaf(sea[i][k], sWc[k * H + c], v);
#pragma unroll
        for (int k = 0; k < 4; k++) v = fmaf(sxl[i][k], sWd[k * H + c], v);
        h[(size_t)e * H + c] = v;
    }
}

// ---------------- BN coefficient computation (float acc) -----------------------
__global__ void bn_coef_kernel(const float* __restrict__ acc,
                               const float* __restrict__ gamma, const float* __restrict__ beta,
                               float* __restrict__ scale, float* __restrict__ shift, int M)
{
    int c = threadIdx.x;
    double mu = (double)acc[c] / (double)M;
    double var = (double)acc[H + c] / (double)M - mu * mu;
    float inv = rsqrtf((float)var + 1e-5f);
    float sc = gamma[c] * inv;
    scale[c] = sc;
    shift[c] = beta[c] - (float)mu * sc;
}

// ---------------- fused GENConv aggregation (CSR gather, fp16 out) -------------
#define RPB 8
__global__ __launch_bounds__(256) void gen_aggr_kernel(
    const float* __restrict__ x, const float* __restrict__ nbg, const float* __restrict__ ebg,
    const float* __restrict__ Wnb, const float* __restrict__ bnb,
    const float* __restrict__ Web, const float* __restrict__ beb,
    const float* __restrict__ bnscale, const float* __restrict__ bnshift,
    const int* __restrict__ src, const int* __restrict__ rowptr, const int* __restrict__ eidx,
    __half* __restrict__ aout, int E, int use_bn)
{
    __shared__ float sWn[4 * H], sWe[4 * H], sbn[H], sbe[H];
    int tid = threadIdx.x;
    for (int i = tid; i < 4 * H; i += 256) { sWn[i] = Wnb[i]; sWe[i] = Web[i]; }
    sbn[tid] = bnb[tid];
    sbe[tid] = beb[tid];
    __syncthreads();
    int c = tid;
    float sc = 1.f, sh = 0.f;
    if (use_bn) { sc = bnscale[c]; sh = bnshift[c]; }
    int d0 = blockIdx.x * RPB;
#pragma unroll
    for (int rr = 0; rr < RPB; rr++) {
        int d = d0 + rr;
        if (d >= E) break;
        int beg = rowptr[d], end = rowptr[d + 1];
        float se = 0.f, sw = 0.f, m0 = 0.f;
        for (int p = beg; p < end; p++) {
            int e = eidx[p];
            int s = src[e];
            float4 nv = *(const float4*)(nbg + (size_t)s * 4);
            float4 ev4 = *(const float4*)(ebg + (size_t)e * 4);
            float nbv = sbn[c];
            nbv = fmaf(nv.x, sWn[c], nbv);
            nbv = fmaf(nv.y, sWn[H + c], nbv);
            nbv = fmaf(nv.z, sWn[2 * H + c], nbv);
            nbv = fmaf(nv.w, sWn[3 * H + c], nbv);
            float ebv = sbe[c];
            ebv = fmaf(ev4.x, sWe[c], ebv);
            ebv = fmaf(ev4.y, sWe[H + c], ebv);
            ebv = fmaf(ev4.z, sWe[2 * H + c], ebv);
            ebv = fmaf(ev4.w, sWe[3 * H + c], ebv);
            float xv = x[(size_t)s * H + c];
            if (use_bn) xv = fmaxf(fmaf(xv, sc, sh), 0.f);
            float mv = fmaxf(xv + nbv + ebv, 0.f) + 1e-7f;
            if (p == beg) {
                m0 = mv;
                se = 1.f;
                sw = mv;
            } else {
                float dmv = fminf(fmaxf(mv - m0, -80.f), 80.f);
                float ee = __expf(dmv);
                se += ee;
                sw = fmaf(ee, mv, sw);
            }
        }
        float xv = x[(size_t)d * H + c];
        if (use_bn) xv = fmaxf(fmaf(xv, sc, sh), 0.f);
        float v = xv + __fdividef(sw, se + 1e-16f);
        aout[(size_t)d * H + c] = __float2half(v);
    }
}

// ---------------- fused node gather + graph pool (BN fused) --------------------
__global__ void node_pool_kernel(const float* __restrict__ h,
                                 const float* __restrict__ bnscale,
                                 const float* __restrict__ bnshift,
                                 const int* __restrict__ rowptr, const int* __restrict__ eidx,
                                 const int* __restrict__ batch,
                                 float* __restrict__ gsum, float* __restrict__ cnt)
{
    int n = blockIdx.x, c = threadIdx.x;
    float sc = bnscale[c], sh = bnshift[c];
    int beg = rowptr[n], end = rowptr[n + 1];
    float acc = 0.f;
    for (int p = beg; p < end; p++) {
        int e = eidx[p];
        acc += fmaf(h[(size_t)e * H + c], sc, sh);
    }
    int b = batch[n];
    atomicAdd(gsum + (size_t)b * H + c, acc);
    if (c == 0) atomicAdd(&cnt[b], 1.0f);
}

__global__ void predict_kernel(const float* __restrict__ gsum, const float* __restrict__ cnt,
                               const float* __restrict__ Wp, const float* __restrict__ bp,
                               float* __restrict__ out)
{
    int g = blockIdx.x, c = threadIdx.x;
    float v = gsum[(size_t)g * H + c] * Wp[c];
    __shared__ float red[8];
#pragma unroll
    for (int o = 16; o > 0; o >>= 1) v += __shfl_down_sync(0xffffffffu, v, o);
    if ((c & 31) == 0) red[c >> 5] = v;
    __syncthreads();
    if (c == 0) {
        float t = 0.f;
#pragma unroll
        for (int i = 0; i < 8; i++) t += red[i];
        out[g] = t / fmaxf(cnt[g], 1.0f) + bp[0];
    }
}

// -------------------------------------------------------------------------------
static void* symA(const void* sym)
{
    void* p = nullptr;
    cudaGetSymbolAddress(&p, sym);
    return p;
}

static void build_csr(const int* dst, int n, int E, int* deg, int* blk,
                      int* rowptr, int* cursor, int* eidx)
{
    int nb = (n + 255) / 256;
    zero_int_kernel<<<nb, 256>>>(deg, n);
    hist_kernel<<<(E + 255) / 256, 256>>>(dst, deg, E);
    scan_block_sums<<<nb, 256>>>(deg, blk, n);
    scan_single_block<<<1, 1024>>>(blk, nb);
    scan_final<<<nb, 256>>>(deg, blk, rowptr, cursor, n, E);
    fill_csr_kernel<<<(E + 255) / 256, 256>>>(dst, cursor, eidx, E);
}

extern "C" void kernel_launch(void* const* d_in, const int* in_sizes, int n_in,
                              void* d_out, int out_size)
{
    const float* x_g       = (const float*)d_in[0];
    const float* ea_g      = (const float*)d_in[1];
    const float* x_lg      = (const float*)d_in[2];
    const float* edb       = (const float*)d_in[3];
    const float* ea_lg     = (const float*)d_in[4];
    const float* W_enc     = (const float*)d_in[5];
    const float* b_enc     = (const float*)d_in[6];
    const float* W_msg     = (const float*)d_in[7];
    const float* b_msg     = (const float*)d_in[8];
    const float* Wg_nb     = (const float*)d_in[9];
    const float* bg_nb     = (const float*)d_in[10];
    const float* Wg_eb     = (const float*)d_in[11];
    const float* bg_eb     = (const float*)d_in[12];
    const float* Wl_nb     = (const float*)d_in[13];
    const float* bl_nb     = (const float*)d_in[14];
    const float* Wl_eb     = (const float*)d_in[15];
    const float* bl_eb     = (const float*)d_in[16];
    const float* W1        = (const float*)d_in[17];
    const float* b1        = (const float*)d_in[18];
    const float* W2        = (const float*)d_in[19];
    const float* b2        = (const float*)d_in[20];
    const float* bn_gamma  = (const float*)d_in[21];
    const float* bn_beta   = (const float*)d_in[22];
    const float* W_pred    = (const float*)d_in[23];
    const float* b_pred    = (const float*)d_in[24];
    const int*   eig       = (const int*)d_in[25];
    const int*   eil       = (const int*)d_in[26];
    const int*   batch     = (const int*)d_in[27];

    int N   = in_sizes[0] / 16;   // 20000
    int Eg  = in_sizes[1] / 16;   // 200000
    int Elg = in_sizes[4] / 4;    // 400000
    const int L = 4;

    cudaFuncSetAttribute(mma_gemm_kernel, cudaFuncAttributeMaxDynamicSharedMemorySize,
                         GEMM_SMEM);

    float* p_AB   = (float*)symA(g_AB);
    float* p_h    = (float*)symA(g_h);
    float* p_nbg  = (float*)symA(g_nbg);
    float* p_ebg  = (float*)symA(g_ebg);
    float* p_bnacc = (float*)symA(g_bnacc);
    float* p_bnsc = (float*)symA(g_bnscale);
    float* p_bnsh = (float*)symA(g_bnshift);
    float* p_gsum = (float*)symA(g_gsum);
    float* p_cnt  = (float*)symA(g_cnt);

    int* p_deg    = (int*)symA(g_deg);
    int* p_cursor = (int*)symA(g_cursor);
    int* p_blk    = (int*)symA(g_blk);
    int* p_rp_lg  = (int*)symA(g_rowptr_lg);
    int* p_ei_lg  = (int*)symA(g_eidx_lg);
    int* p_rp_g   = (int*)symA(g_rowptr_g);
    int* p_ei_g   = (int*)symA(g_eidx_g);

    __half* p_node = (__half*)symA(g_node);
    __half* p_act  = (__half*)symA(g_act);
    __half* p_hid  = (__half*)symA(g_hid);
    __half* p_wthi = (__half*)symA(g_wthi);
    __half* p_wtlo = (__half*)symA(g_wtlo);

    const int* src_g = eig;
    const int* dst_g = eig + Eg;
    const int* src_l = eil;
    const int* dst_l = eil + Elg;

    int mtE = (Eg + 127) / 128;   // 1563
    int mtN = (N + 127) / 128;    // 157

    // --- CSR builds ---
    build_csr(dst_l, Eg, Elg, p_deg, p_blk, p_rp_lg, p_cursor, p_ei_lg);
    build_csr(dst_g, N, Eg, p_deg, p_blk, p_rp_g, p_cursor, p_ei_g);

    // --- weight transpose + split ---
    tsplit_kernel<<<(65536 + 255) / 256, 256>>>(W_msg,           p_wthi + OFF_WMSG,         p_wtlo + OFF_WMSG,         256, 256);
    tsplit_kernel<<<(65536 + 255) / 256, 256>>>(W_msg + 256 * H, p_wthi + OFF_WMSG + 65536, p_wtlo + OFF_WMSG + 65536, 256, 256);
    for (int l = 0; l < L; l++) {
        tsplit_kernel<<<(131072 + 255) / 256, 256>>>(
            W1 + (size_t)l * 131072, p_wthi + OFF_W1T + l * 131072, p_wtlo + OFF_W1T + l * 131072, 256, 512);
        tsplit_kernel<<<(131072 + 255) / 256, 256>>>(
            W2 + (size_t)l * 131072, p_wthi + OFF_W2T + l * 131072, p_wtlo + OFF_W2T + l * 131072, 512, 256);
    }

    // --- node encoder + combined msg GEMM (N=512) ---
    enc_kernel<<<N, 256>>>(x_g, W_enc, b_enc, p_node);
    {
        dim3 grid(4, mtN);   // n fast
        mma_gemm_kernel<<<grid, 256, GEMM_SMEM>>>(
            p_node, p_wthi + OFF_WMSG, p_wtlo + OFF_WMSG,
            nullptr, nullptr, p_AB, nullptr, nullptr, N, 512, 256, 0);
    }
    basis4_kernel<<<(Eg + 255) / 256, 256>>>(edb,   Wg_nb, bg_nb, p_nbg, Eg);
    basis4_kernel<<<(Elg + 255) / 256, 256>>>(ea_lg, Wg_eb, bg_eb, p_ebg, Elg);
    msg_edge_kernel<<<(Eg + MEPB - 1) / MEPB, 256>>>(
        p_AB, ea_g, x_lg, W_msg + 512 * H, W_msg + 528 * H, b_msg,
        src_g, dst_g, p_h, Eg);

    // layer-0 h has no BN stats from a GEMM; compute stats during layer 0's GEMM2.
    // --- 4 GENConv layers ---
    for (int l = 0; l < L; l++) {
        int use_bn = (l > 0) ? 1 : 0;
        if (use_bn) {
            // stats for h were accumulated by previous layer's GEMM2 epilogue
            bn_coef_kernel<<<1, 256>>>(p_bnacc, bn_gamma + (l - 1) * H, bn_beta + (l - 1) * H,
                                       p_bnsc, p_bnsh, Eg);
        }
        gen_aggr_kernel<<<(Eg + RPB - 1) / RPB, 256>>>(
            p_h, p_nbg, p_ebg,
            Wl_nb + l * 4 * H, bl_nb + l * H,
            Wl_eb + l * 4 * H, bl_eb + l * H,
            p_bnsc, p_bnsh, src_l, p_rp_lg, p_ei_lg,
            p_act, Eg, use_bn);

        // GEMM1: hid = relu(act @ W1 + b1), fp16 out
        {
            dim3 grid(4, mtE);   // n fast
            mma_gemm_kernel<<<grid, 256, GEMM_SMEM>>>(
                p_act, p_wthi + OFF_W1T + l * 131072, p_wtlo + OFF_W1T + l * 131072,
                b1 + l * 512, nullptr, nullptr, p_hid, nullptr,
                Eg, 512, 256, 1 | 2 | 8);
        }
        // GEMM2: h = hid @ W2 + b2 (+ residual for l>0), fp32 out + fused BN stats
        cudaMemsetAsync(p_bnacc, 0, 2 * H * sizeof(float));
        {
            dim3 grid(2, mtE);   // n fast
            mma_gemm_kernel<<<grid, 256, GEMM_SMEM>>>(
                p_hid, p_wthi + OFF_W2T + l * 131072, p_wtlo + OFF_W2T + l * 131072,
                b2 + l * 256, (l > 0) ? p_h : nullptr, p_h, nullptr, p_bnacc,
                Eg, 256, 512, ((l > 0) ? (1 | 4) : 1) | 32);
        }
    }

    // --- final BN coefs (stats from layer-3 GEMM2) + fused node gather/pool ---
    bn_coef_kernel<<<1, 256>>>(p_bnacc, bn_gamma + 3 * H, bn_beta + 3 * H, p_bnsc, p_bnsh, Eg);

    cudaMemsetAsync(p_gsum, 0, NGRAPH * H * sizeof(float));
    cudaMemsetAsync(p_cnt,  0, NGRAPH * sizeof(float));
    node_pool_kernel<<<N, 256>>>(p_h, p_bnsc, p_bnsh, p_rp_g, p_ei_g, batch, p_gsum, p_cnt);
    predict_kernel<<<NGRAPH, 256>>>(p_gsum, p_cnt, W_pred, b_pred, (float*)d_out);
}

// round 13
// speedup vs baseline: 1.5029x; 1.0002x over previous
#include <cuda_runtime.h>
#include <cuda_fp16.h>
#include <cstdint>

#define H 256
#define NGRAPH 128
#define MAXN   20224
#define MAXEG  200192
#define MAXELG 400128

// ---------------- scratch ----------------
__device__ float g_AB[(size_t)MAXN * 512];
__device__ float g_h[(size_t)MAXEG * H];
__device__ float g_nbg[(size_t)MAXEG * 4];
__device__ float g_ebg[(size_t)MAXELG * 4];
__device__ float g_bnacc[2 * H];
__device__ float g_bnscale[H];
__device__ float g_bnshift[H];
__device__ float g_gsum[NGRAPH * H];
__device__ float g_cnt[NGRAPH];

// CSR scratch
__device__ int g_deg[MAXEG];
__device__ int g_cursor[MAXEG];
__device__ int g_blk[1024];
__device__ int g_rowptr_lg[MAXEG + 1];
__device__ int g_eidx_lg[MAXELG];
__device__ int g_rowptr_g[MAXN + 1];
__device__ int g_eidx_g[MAXEG];

// fp16 activation buffers (pad rows never written -> stay zero)
__device__ __half g_node[(size_t)MAXN * H];
__device__ __half g_act[(size_t)MAXEG * H];
__device__ __half g_hid[(size_t)MAXEG * 2 * H];

// transposed/split fp16 weights arena
#define OFF_WMSG 0
#define OFF_W1T  (512 * 256)
#define OFF_W2T  (OFF_W1T + 4 * 131072)
#define WT_TOTAL (OFF_W2T + 4 * 131072)
__device__ __half g_wthi[WT_TOTAL];
__device__ __half g_wtlo[WT_TOTAL];

// ======================= helpers =======================
__device__ __forceinline__ uint32_t smem_u32(const void* p) {
    uint32_t a;
    asm("{ .reg .u64 t; cvta.to.shared.u64 t, %1; cvt.u32.u64 %0, t; }" : "=r"(a) : "l"(p));
    return a;
}
#define CP16(dst, src) \
    asm volatile("cp.async.cg.shared.global [%0], [%1], 16;" :: "r"(dst), "l"(src) : "memory")
#define CP_COMMIT() asm volatile("cp.async.commit_group;" ::: "memory")
#define CP_WAIT1()  asm volatile("cp.async.wait_group 1;" ::: "memory")
#define CP_WAIT0()  asm volatile("cp.async.wait_group 0;" ::: "memory")

__device__ __forceinline__ void ldm4(uint32_t (&r)[4], uint32_t addr) {
    asm volatile("ldmatrix.sync.aligned.m8n8.x4.shared.b16 {%0,%1,%2,%3}, [%4];"
                 : "=r"(r[0]), "=r"(r[1]), "=r"(r[2]), "=r"(r[3]) : "r"(addr));
}
__device__ __forceinline__ void mma_f16(float (&d)[4], const uint32_t (&a)[4], const uint32_t* b) {
    asm volatile(
        "mma.sync.aligned.m16n8k16.row.col.f32.f16.f16.f32 "
        "{%0,%1,%2,%3}, {%4,%5,%6,%7}, {%8,%9}, {%0,%1,%2,%3};"
        : "+f"(d[0]), "+f"(d[1]), "+f"(d[2]), "+f"(d[3])
        : "r"(a[0]), "r"(a[1]), "r"(a[2]), "r"(a[3]), "r"(b[0]), "r"(b[1]));
}

// ======================= CSR build kernels =======================
__global__ void zero_int_kernel(int* a, int n)
{
    int i = blockIdx.x * 256 + threadIdx.x;
    if (i < n) a[i] = 0;
}
__global__ void hist_kernel(const int* __restrict__ dst, int* __restrict__ deg, int E)
{
    int i = blockIdx.x * 256 + threadIdx.x;
    if (i < E) atomicAdd(&deg[dst[i]], 1);
}
__global__ void scan_block_sums(const int* __restrict__ deg, int* __restrict__ blk, int n)
{
    __shared__ int sd[256];
    int t = threadIdx.x;
    int i = blockIdx.x * 256 + t;
    sd[t] = (i < n) ? deg[i] : 0;
    __syncthreads();
    for (int o = 128; o > 0; o >>= 1) {
        if (t < o) sd[t] += sd[t + o];
        __syncthreads();
    }
    if (t == 0) blk[blockIdx.x] = sd[0];
}
__global__ void scan_single_block(int* blk, int nb)
{
    __shared__ int tmp[1024];
    int t = threadIdx.x;
    int v = (t < nb) ? blk[t] : 0;
    tmp[t] = v;
    __syncthreads();
    for (int o = 1; o < 1024; o <<= 1) {
        int u = (t >= o) ? tmp[t - o] : 0;
        __syncthreads();
        tmp[t] += u;
        __syncthreads();
    }
    if (t < nb) blk[t] = tmp[t] - v;
}
__global__ void scan_final(const int* __restrict__ deg, const int* __restrict__ blk,
                           int* __restrict__ rowptr, int* __restrict__ cursor, int n, int E)
{
    __shared__ int tmp[256];
    int t = threadIdx.x;
    int i = blockIdx.x * 256 + t;
    int v = (i < n) ? deg[i] : 0;
    tmp[t] = v;
    __syncthreads();
    for (int o = 1; o < 256; o <<= 1) {
        int u = (t >= o) ? tmp[t - o] : 0;
        __syncthreads();
        tmp[t] += u;
        __syncthreads();
    }
    int excl = tmp[t] - v + blk[blockIdx.x];
    if (i < n) { rowptr[i] = excl; cursor[i] = excl; }
    if (blockIdx.x == 0 && t == 0) rowptr[n] = E;
}
__global__ void fill_csr_kernel(const int* __restrict__ dst, int* __restrict__ cursor,
                                int* __restrict__ eidx, int E)
{
    int e = blockIdx.x * 256 + threadIdx.x;
    if (e < E) {
        int p = atomicAdd(&cursor[dst[e]], 1);
        eidx[p] = e;
    }
}

// ======================= mma.sync 2-term fp16 GEMM =======================
// C[M,N] = A[M,K] @ W[K,N]; A fp16 [M,K] row-major, W transposed split fp16
// (Bhi,Blo) [N,K] row-major.  C = A*Bhi + A*Blo (fp32 acc).
// CTA 128x128, 8 warps of 64x32, BK=32, 3 stages, 2 CTAs/SM. n-tile fast in grid.
// Mainloop issues all hi-term mma before lo-term mma: same-accumulator reuse
// distance 2 -> 16 to break tensor-pipe RAW chains.
// flags: 1=bias, 2=relu, 4=residual fp32, 8=fp16 out, 32=BN stats (float bnacc[2N])
#define RB 80
#define TILE_B (128 * RB)
#define SO_A   0
#define SO_BHI (1 * TILE_B)
#define SO_BLO (2 * TILE_B)
#define STAGE_B (3 * TILE_B)
#define GEMM_SMEM (3 * STAGE_B)

__device__ __forceinline__ void load_stage(uint32_t sbase,
    const __half* __restrict__ A, const __half* __restrict__ B_hi,
    const __half* __restrict__ B_lo,
    int K, int m0, int n0, int k0, int tid)
{
#pragma unroll
    for (int i = 0; i < 2; i++) {
        int g = tid + i * 256;
        int row = g >> 2, ch = g & 3;
        uint32_t so = (uint32_t)row * RB + (uint32_t)ch * 16;
        size_t ao = (size_t)(m0 + row) * K + k0 + ch * 8;
        size_t bo = (size_t)(n0 + row) * K + k0 + ch * 8;
        CP16(sbase + SO_A + so, A + ao);
        CP16(sbase + SO_BHI + so, B_hi + bo);
        CP16(sbase + SO_BLO + so, B_lo + bo);
    }
}

__global__ __launch_bounds__(256, 2) void mma_gemm_kernel(
    const __half* __restrict__ A,
    const __half* __restrict__ Bhi, const __half* __restrict__ Blo,
    const float* __restrict__ bias, const float* __restrict__ res,
    float* __restrict__ Cf, __half* __restrict__ Ch, float* __restrict__ bnacc,
    int M, int N, int K, int flags)
{
    extern __shared__ __align__(128) char smem[];
    uint32_t sb = smem_u32(smem);
    int tid = threadIdx.x;
    int wid = tid >> 5, lane = tid & 31;
    int m0 = blockIdx.y * 128, n0 = blockIdx.x * 128;
    int nk = K >> 5;

    load_stage(sb, A, Bhi, Blo, K, m0, n0, 0, tid);
    CP_COMMIT();
    load_stage(sb + STAGE_B, A, Bhi, Blo, K, m0, n0, 32, tid);
    CP_COMMIT();

    float acc[4][4][4];
#pragma unroll
    for (int i = 0; i < 4; i++)
#pragma unroll
        for (int j = 0; j < 4; j++)
#pragma unroll
            for (int q = 0; q < 4; q++) acc[i][j][q] = 0.f;

    int mo = (wid & 1) * 64, no = (wid >> 1) * 32;
    int a_row = mo + (lane & 15);
    int a_k8  = lane >> 4;
    int b_row = ((lane >> 4) << 3) + (lane & 7);
    int b_k8  = (lane >> 3) & 1;

    for (int k = 0; k < nk; k++) {
        if (k == nk - 1) { CP_WAIT0(); } else { CP_WAIT1(); }
        __syncthreads();
        uint32_t base = sb + (uint32_t)(k % 3) * STAGE_B;
        if (k + 2 < nk)
            load_stage(sb + (uint32_t)((k + 2) % 3) * STAGE_B, A, Bhi, Blo,
                       K, m0, n0, (k + 2) * 32, tid);
        CP_COMMIT();
#pragma unroll
        for (int k16 = 0; k16 < 2; k16++) {
            int kk8 = k16 * 2;
            uint32_t ah[4][4], bh[2][4], bl[2][4];
#pragma unroll
            for (int i = 0; i < 4; i++) {
                uint32_t aaddr = base + SO_A + (uint32_t)(a_row + i * 16) * RB
                               + (uint32_t)(kk8 + a_k8) * 16;
                ldm4(ah[i], aaddr);
            }
#pragma unroll
            for (int j = 0; j < 2; j++) {
                uint32_t baddr = base + SO_BHI + (uint32_t)(no + j * 16 + b_row) * RB
                               + (uint32_t)(kk8 + b_k8) * 16;
                ldm4(bh[j], baddr);
                ldm4(bl[j], baddr + (SO_BLO - SO_BHI));
            }
            // hi pass: each accumulator touched exactly once
#pragma unroll
            for (int j = 0; j < 2; j++)
#pragma unroll
                for (int i = 0; i < 4; i++) {
                    mma_f16(acc[i][2 * j],     ah[i], &bh[j][0]);
                    mma_f16(acc[i][2 * j + 1], ah[i], &bh[j][2]);
                }
            // lo pass
#pragma unroll
            for (int j = 0; j < 2; j++)
#pragma unroll
                for (int i = 0; i < 4; i++) {
                    mma_f16(acc[i][2 * j],     ah[i], &bl[j][0]);
                    mma_f16(acc[i][2 * j + 1], ah[i], &bl[j][2]);
                }
        }
    }

    // epilogue (+ optional fused BN statistics)
    float st[4][2], sq[4][2];
#pragma unroll
    for (int nb = 0; nb < 4; nb++) {
        st[nb][0] = st[nb][1] = 0.f;
        sq[nb][0] = sq[nb][1] = 0.f;
    }
#pragma unroll
    for (int i = 0; i < 4; i++) {
        int r0 = m0 + mo + i * 16 + (lane >> 2);
#pragma unroll
        for (int half = 0; half < 2; half++) {
            int r = r0 + half * 8;
            if (r >= M) continue;
#pragma unroll
            for (int nb = 0; nb < 4; nb++) {
                int col = n0 + no + nb * 8 + 2 * (lane & 3);
                float v0 = acc[i][nb][half * 2 + 0];
                float v1 = acc[i][nb][half * 2 + 1];
                if (flags & 1) { v0 += bias[col]; v1 += bias[col + 1]; }
                if (flags & 4) {
                    float2 t = *(const float2*)(res + (size_t)r * N + col);
                    v0 += t.x; v1 += t.y;
                }
                if (flags & 2) { v0 = fmaxf(v0, 0.f); v1 = fmaxf(v1, 0.f); }
                if (flags & 32) {
                    st[nb][0] += v0; sq[nb][0] = fmaf(v0, v0, sq[nb][0]);
                    st[nb][1] += v1; sq[nb][1] = fmaf(v1, v1, sq[nb][1]);
                }
                if (flags & 8) {
                    *(__half2*)(Ch + (size_t)r * N + col) =
                        __halves2half2(__float2half(v0), __float2half(v1));
                } else {
                    *(float2*)(Cf + (size_t)r * N + col) = make_float2(v0, v1);
                }
            }
        }
    }
    if (flags & 32) {
#pragma unroll
        for (int nb = 0; nb < 4; nb++)
#pragma unroll
            for (int w = 0; w < 2; w++) {
                float s = st[nb][w], q = sq[nb][w];
                s += __shfl_xor_sync(0xffffffffu, s, 4);
                q += __shfl_xor_sync(0xffffffffu, q, 4);
                s += __shfl_xor_sync(0xffffffffu, s, 8);
                q += __shfl_xor_sync(0xffffffffu, q, 8);
                s += __shfl_xor_sync(0xffffffffu, s, 16);
                q += __shfl_xor_sync(0xffffffffu, q, 16);
                if ((lane >> 2) == 0) {
                    int col = n0 + no + nb * 8 + 2 * (lane & 3) + w;
                    atomicAdd(&bnacc[col], s);
                    atomicAdd(&bnacc[N + col], q);
                }
            }
    }
}

// ---------------- weight transpose+split (fp16 hi/lo) --------------------------
__global__ void tsplit_kernel(const float* __restrict__ W,
                              __half* __restrict__ thi, __half* __restrict__ tlo,
                              int K, int N)
{
    int idx = blockIdx.x * 256 + threadIdx.x;
    if (idx >= K * N) return;
    int k = idx / N, n = idx % N;
    float w = W[idx];
    __half hi = __float2half(w);
    __half lo = __float2half(w - __half2float(hi));
    thi[(size_t)n * K + k] = hi;
    tlo[(size_t)n * K + k] = lo;
}

// ---------------- node encoder (fp16 out) --------------------------------------
__global__ void enc_kernel(const float* __restrict__ xg, const float* __restrict__ W,
                           const float* __restrict__ b, __half* __restrict__ out)
{
    __shared__ float sx[16];
    int n = blockIdx.x, c = threadIdx.x;
    if (c < 16) sx[c] = xg[(size_t)n * 16 + c];
    __syncthreads();
    float v = b[c];
#pragma unroll
    for (int k = 0; k < 16; k++) v = fmaf(sx[k], W[k * H + c], v);
    out[(size_t)n * H + c] = __float2half(v);
}

// ---------------- combined tiny [.,4]@[4,4]+b projections ----------------------
__global__ void basis4_both_kernel(const float* __restrict__ in1, const float* __restrict__ W1,
                                   const float* __restrict__ b1v, float* __restrict__ out1, int E1,
                                   const float* __restrict__ in2, const float* __restrict__ W2,
                                   const float* __restrict__ b2v, float* __restrict__ out2, int E2)
{
    int e = blockIdx.x * blockDim.x + threadIdx.x;
    const float* in; const float* W; const float* b; float* out;
    if (e < E1) { in = in1; W = W1; b = b1v; out = out1; }
    else { e -= E1; if (e >= E2) return; in = in2; W = W2; b = b2v; out = out2; }
    float4 x = *(const float4*)(in + (size_t)e * 4);
    float o0 = b[0] + x.x * W[0] + x.y * W[4] + x.z * W[8]  + x.w * W[12];
    float o1 = b[1] + x.x * W[1] + x.y * W[5] + x.z * W[9]  + x.w * W[13];
    float o2 = b[2] + x.x * W[2] + x.y * W[6] + x.z * W[10] + x.w * W[14];
    float o3 = b[3] + x.x * W[3] + x.y * W[7] + x.z * W[11] + x.w * W[15];
    *(float4*)(out + (size_t)e * 4) = make_float4(o0, o1, o2, o3);
}

// ---------------- fused first-message ------------------------------------------
#define MEPB 16
__global__ __launch_bounds__(256) void msg_edge_kernel(
    const float* __restrict__ AB,
    const float* __restrict__ ea, const float* __restrict__ xlg,
    const float* __restrict__ Wc, const float* __restrict__ Wd,
    const float* __restrict__ bmsg,
    const int* __restrict__ srcg, const int* __restrict__ dstg,
    float* __restrict__ h, int Eg)
{
    __shared__ float sWc[16 * H];
    __shared__ float sWd[4 * H];
    __shared__ float sb[H];
    __shared__ float sea[MEPB][16];
    __shared__ float sxl[MEPB][4];
    int tid = threadIdx.x;
    for (int i = tid; i < 16 * H; i += 256) sWc[i] = Wc[i];
    for (int i = tid; i < 4 * H; i += 256) sWd[i] = Wd[i];
    sb[tid] = bmsg[tid];
    int e0 = blockIdx.x * MEPB;
    for (int i = tid; i < MEPB * 16; i += 256) {
        int e = e0 + i / 16;
        if (e < Eg) sea[i / 16][i % 16] = ea[(size_t)e * 16 + (i % 16)];
    }
    for (int i = tid; i < MEPB * 4; i += 256) {
        int e = e0 + i / 4;
        if (e < Eg) sxl[i / 4][i % 4] = xlg[(size_t)e * 4 + (i % 4)];
    }
    __syncthreads();
    int c = tid;
    for (int i = 0; i < MEPB; i++) {
        int e = e0 + i;
        if (e >= Eg) break;
        int s = srcg[e], d = dstg[e];
        float v = AB[(size_t)s * 512 + c] + AB[(size_t)d * 512 + 256 + c] + sb[c];
#pragma unroll
        for (int k = 0; k < 16; k++) v = fmaf(sea[i][k], sWc[k * H + c], v);
#pragma unroll
        for (int k = 0; k < 4; k++) v = fmaf(sxl[i][k], sWd[k * H + c], v);
        h[(size_t)e * H + c] = v;
    }
}

// ---------------- BN coefficient computation (float acc) -----------------------
__global__ void bn_coef_kernel(const float* __restrict__ acc,
                               const float* __restrict__ gamma, const float* __restrict__ beta,
                               float* __restrict__ scale, float* __restrict__ shift, int M)
{
    int c = threadIdx.x;
    double mu = (double)acc[c] / (double)M;
    double var = (double)acc[H + c] / (double)M - mu * mu;
    float inv = rsqrtf((float)var + 1e-5f);
    float sc = gamma[c] * inv;
    scale[c] = sc;
    shift[c] = beta[c] - (float)mu * sc;
}

// ---------------- fused GENConv aggregation (CSR gather, fp16 out) -------------
#define RPB 8
__global__ __launch_bounds__(256) void gen_aggr_kernel(
    const float* __restrict__ x, const float* __restrict__ nbg, const float* __restrict__ ebg,
    const float* __restrict__ Wnb, const float* __restrict__ bnb,
    const float* __restrict__ Web, const float* __restrict__ beb,
    const float* __restrict__ bnscale, const float* __restrict__ bnshift,
    const int* __restrict__ src, const int* __restrict__ rowptr, const int* __restrict__ eidx,
    __half* __restrict__ aout, int E, int use_bn)
{
    __shared__ float sWn[4 * H], sWe[4 * H], sbn[H], sbe[H];
    int tid = threadIdx.x;
    for (int i = tid; i < 4 * H; i += 256) { sWn[i] = Wnb[i]; sWe[i] = Web[i]; }
    sbn[tid] = bnb[tid];
    sbe[tid] = beb[tid];
    __syncthreads();
    int c = tid;
    float sc = 1.f, sh = 0.f;
    if (use_bn) { sc = bnscale[c]; sh = bnshift[c]; }
    int d0 = blockIdx.x * RPB;
#pragma unroll
    for (int rr = 0; rr < RPB; rr++) {
        int d = d0 + rr;
        if (d >= E) break;
        int beg = rowptr[d], end = rowptr[d + 1];
        float se = 0.f, sw = 0.f, m0 = 0.f;
        for (int p = beg; p < end; p++) {
            int e = eidx[p];
            int s = src[e];
            float4 nv = *(const float4*)(nbg + (size_t)s * 4);
            float4 ev4 = *(const float4*)(ebg + (size_t)e * 4);
            float nbv = sbn[c];
            nbv = fmaf(nv.x, sWn[c], nbv);
            nbv = fmaf(nv.y, sWn[H + c], nbv);
            nbv = fmaf(nv.z, sWn[2 * H + c], nbv);
            nbv = fmaf(nv.w, sWn[3 * H + c], nbv);
            float ebv = sbe[c];
            ebv = fmaf(ev4.x, sWe[c], ebv);
            ebv = fmaf(ev4.y, sWe[H + c], ebv);
            ebv = fmaf(ev4.z, sWe[2 * H + c], ebv);
            ebv = fmaf(ev4.w, sWe[3 * H + c], ebv);
            float xv = x[(size_t)s * H + c];
            if (use_bn) xv = fmaxf(fmaf(xv, sc, sh), 0.f);
            float mv = fmaxf(xv + nbv + ebv, 0.f) + 1e-7f;
            if (p == beg) {
                m0 = mv;
                se = 1.f;
                sw = mv;
            } else {
                float dmv = fminf(fmaxf(mv - m0, -80.f), 80.f);
                float ee = __expf(dmv);
                se += ee;
                sw = fmaf(ee, mv, sw);
            }
        }
        float xv = x[(size_t)d * H + c];
        if (use_bn) xv = fmaxf(fmaf(xv, sc, sh), 0.f);
        float v = xv + __fdividef(sw, se + 1e-16f);
        aout[(size_t)d * H + c] = __float2half(v);
    }
}

// ---------------- fused node gather + graph pool (BN fused) --------------------
__global__ void node_pool_kernel(const float* __restrict__ h,
                                 const float* __restrict__ bnscale,
                                 const float* __restrict__ bnshift,
                                 const int* __restrict__ rowptr, const int* __restrict__ eidx,
                                 const int* __restrict__ batch,
                                 float* __restrict__ gsum, float* __restrict__ cnt)
{
    int n = blockIdx.x, c = threadIdx.x;
    float sc = bnscale[c], sh = bnshift[c];
    int beg = rowptr[n], end = rowptr[n + 1];
    float acc = 0.f;
    for (int p = beg; p < end; p++) {
        int e = eidx[p];
        acc += fmaf(h[(size_t)e * H + c], sc, sh);
    }
    int b = batch[n];
    atomicAdd(gsum + (size_t)b * H + c, acc);
    if (c == 0) atomicAdd(&cnt[b], 1.0f);
}

__global__ void predict_kernel(const float* __restrict__ gsum, const float* __restrict__ cnt,
                               const float* __restrict__ Wp, const float* __restrict__ bp,
                               float* __restrict__ out)
{
    int g = blockIdx.x, c = threadIdx.x;
    float v = gsum[(size_t)g * H + c] * Wp[c];
    __shared__ float red[8];
#pragma unroll
    for (int o = 16; o > 0; o >>= 1) v += __shfl_down_sync(0xffffffffu, v, o);
    if ((c & 31) == 0) red[c >> 5] = v;
    __syncthreads();
    if (c == 0) {
        float t = 0.f;
#pragma unroll
        for (int i = 0; i < 8; i++) t += red[i];
        out[g] = t / fmaxf(cnt[g], 1.0f) + bp[0];
    }
}

// -------------------------------------------------------------------------------
static void* symA(const void* sym)
{
    void* p = nullptr;
    cudaGetSymbolAddress(&p, sym);
    return p;
}

static void build_csr(const int* dst, int n, int E, int* deg, int* blk,
                      int* rowptr, int* cursor, int* eidx)
{
    int nb = (n + 255) / 256;
    zero_int_kernel<<<nb, 256>>>(deg, n);
    hist_kernel<<<(E + 255) / 256, 256>>>(dst, deg, E);
    scan_block_sums<<<nb, 256>>>(deg, blk, n);
    scan_single_block<<<1, 1024>>>(blk, nb);
    scan_final<<<nb, 256>>>(deg, blk, rowptr, cursor, n, E);
    fill_csr_kernel<<<(E + 255) / 256, 256>>>(dst, cursor, eidx, E);
}

extern "C" void kernel_launch(void* const* d_in, const int* in_sizes, int n_in,
                              void* d_out, int out_size)
{
    const float* x_g       = (const float*)d_in[0];
    const float* ea_g      = (const float*)d_in[1];
    const float* x_lg      = (const float*)d_in[2];
    const float* edb       = (const float*)d_in[3];
    const float* ea_lg     = (const float*)d_in[4];
    const float* W_enc     = (const float*)d_in[5];
    const float* b_enc     = (const float*)d_in[6];
    const float* W_msg     = (const float*)d_in[7];
    const float* b_msg     = (const float*)d_in[8];
    const float* Wg_nb     = (const float*)d_in[9];
    const float* bg_nb     = (const float*)d_in[10];
    const float* Wg_eb     = (const float*)d_in[11];
    const float* bg_eb     = (const float*)d_in[12];
    const float* Wl_nb     = (const float*)d_in[13];
    const float* bl_nb     = (const float*)d_in[14];
    const float* Wl_eb     = (const float*)d_in[15];
    const float* bl_eb     = (const float*)d_in[16];
    const float* W1        = (const float*)d_in[17];
    const float* b1        = (const float*)d_in[18];
    const float* W2        = (const float*)d_in[19];
    const float* b2        = (const float*)d_in[20];
    const float* bn_gamma  = (const float*)d_in[21];
    const float* bn_beta   = (const float*)d_in[22];
    const float* W_pred    = (const float*)d_in[23];
    const float* b_pred    = (const float*)d_in[24];
    const int*   eig       = (const int*)d_in[25];
    const int*   eil       = (const int*)d_in[26];
    const int*   batch     = (const int*)d_in[27];

    int N   = in_sizes[0] / 16;   // 20000
    int Eg  = in_sizes[1] / 16;   // 200000
    int Elg = in_sizes[4] / 4;    // 400000
    const int L = 4;

    cudaFuncSetAttribute(mma_gemm_kernel, cudaFuncAttributeMaxDynamicSharedMemorySize,
                         GEMM_SMEM);

    float* p_AB   = (float*)symA(g_AB);
    float* p_h    = (float*)symA(g_h);
    float* p_nbg  = (float*)symA(g_nbg);
    float* p_ebg  = (float*)symA(g_ebg);
    float* p_bnacc = (float*)symA(g_bnacc);
    float* p_bnsc = (float*)symA(g_bnscale);
    float* p_bnsh = (float*)symA(g_bnshift);
    float* p_gsum = (float*)symA(g_gsum);
    float* p_cnt  = (float*)symA(g_cnt);

    int* p_deg    = (int*)symA(g_deg);
    int* p_cursor = (int*)symA(g_cursor);
    int* p_blk    = (int*)symA(g_blk);
    int* p_rp_lg  = (int*)symA(g_rowptr_lg);
    int* p_ei_lg  = (int*)symA(g_eidx_lg);
    int* p_rp_g   = (int*)symA(g_rowptr_g);
    int* p_ei_g   = (int*)symA(g_eidx_g);

    __half* p_node = (__half*)symA(g_node);
    __half* p_act  = (__half*)symA(g_act);
    __half* p_hid  = (__half*)symA(g_hid);
    __half* p_wthi = (__half*)symA(g_wthi);
    __half* p_wtlo = (__half*)symA(g_wtlo);

    const int* src_g = eig;
    const int* dst_g = eig + Eg;
    const int* src_l = eil;
    const int* dst_l = eil + Elg;

    int mtE = (Eg + 127) / 128;   // 1563
    int mtN = (N + 127) / 128;    // 157

    // --- CSR builds ---
    build_csr(dst_l, Eg, Elg, p_deg, p_blk, p_rp_lg, p_cursor, p_ei_lg);
    build_csr(dst_g, N, Eg, p_deg, p_blk, p_rp_g, p_cursor, p_ei_g);

    // --- weight transpose + split ---
    tsplit_kernel<<<(65536 + 255) / 256, 256>>>(W_msg,           p_wthi + OFF_WMSG,         p_wtlo + OFF_WMSG,         256, 256);
    tsplit_kernel<<<(65536 + 255) / 256, 256>>>(W_msg + 256 * H, p_wthi + OFF_WMSG + 65536, p_wtlo + OFF_WMSG + 65536, 256, 256);
    for (int l = 0; l < L; l++) {
        tsplit_kernel<<<(131072 + 255) / 256, 256>>>(
            W1 + (size_t)l * 131072, p_wthi + OFF_W1T + l * 131072, p_wtlo + OFF_W1T + l * 131072, 256, 512);
        tsplit_kernel<<<(131072 + 255) / 256, 256>>>(
            W2 + (size_t)l * 131072, p_wthi + OFF_W2T + l * 131072, p_wtlo + OFF_W2T + l * 131072, 512, 256);
    }

    // --- node encoder + combined msg GEMM (N=512) ---
    enc_kernel<<<N, 256>>>(x_g, W_enc, b_enc, p_node);
    {
        dim3 grid(4, mtN);   // n fast
        mma_gemm_kernel<<<grid, 256, GEMM_SMEM>>>(
            p_node, p_wthi + OFF_WMSG, p_wtlo + OFF_WMSG,
            nullptr, nullptr, p_AB, nullptr, nullptr, N, 512, 256, 0);
    }
    basis4_both_kernel<<<(Eg + Elg + 255) / 256, 256>>>(
        edb, Wg_nb, bg_nb, p_nbg, Eg,
        ea_lg, Wg_eb, bg_eb, p_ebg, Elg);
    msg_edge_kernel<<<(Eg + MEPB - 1) / MEPB, 256>>>(
        p_AB, ea_g, x_lg, W_msg + 512 * H, W_msg + 528 * H, b_msg,
        src_g, dst_g, p_h, Eg);

    // --- 4 GENConv layers ---
    for (int l = 0; l < L; l++) {
        int use_bn = (l > 0) ? 1 : 0;
        if (use_bn) {
            // stats for h were accumulated by previous layer's GEMM2 epilogue
            bn_coef_kernel<<<1, 256>>>(p_bnacc, bn_gamma + (l - 1) * H, bn_beta + (l - 1) * H,
                                       p_bnsc, p_bnsh, Eg);
        }
        gen_aggr_kernel<<<(Eg + RPB - 1) / RPB, 256>>>(
            p_h, p_nbg, p_ebg,
            Wl_nb + l * 4 * H, bl_nb + l * H,
            Wl_eb + l * 4 * H, bl_eb + l * H,
            p_bnsc, p_bnsh, src_l, p_rp_lg, p_ei_lg,
            p_act, Eg, use_bn);

        // GEMM1: hid = relu(act @ W1 + b1), fp16 out
        {
            dim3 grid(4, mtE);   // n fast
            mma_gemm_kernel<<<grid, 256, GEMM_SMEM>>>(
                p_act, p_wthi + OFF_W1T + l * 131072, p_wtlo + OFF_W1T + l * 131072,
                b1 + l * 512, nullptr, nullptr, p_hid, nullptr,
                Eg, 512, 256, 1 | 2 | 8);
        }
        // GEMM2: h = hid @ W2 + b2 (+ residual for l>0), fp32 out + fused BN stats
        cudaMemsetAsync(p_bnacc, 0, 2 * H * sizeof(float));
        {
            dim3 grid(2, mtE);   // n fast
            mma_gemm_kernel<<<grid, 256, GEMM_SMEM>>>(
                p_hid, p_wthi + OFF_W2T + l * 131072, p_wtlo + OFF_W2T + l * 131072,
                b2 + l * 256, (l > 0) ? p_h : nullptr, p_h, nullptr, p_bnacc,
                Eg, 256, 512, ((l > 0) ? (1 | 4) : 1) | 32);
        }
    }

    // --- final BN coefs (stats from layer-3 GEMM2) + fused node gather/pool ---
    bn_coef_kernel<<<1, 256>>>(p_bnacc, bn_gamma + 3 * H, bn_beta + 3 * H, p_bnsc, p_bnsh, Eg);

    cudaMemsetAsync(p_gsum, 0, NGRAPH * H * sizeof(float));
    cudaMemsetAsync(p_cnt,  0, NGRAPH * sizeof(float));
    node_pool_kernel<<<N, 256>>>(p_h, p_bnsc, p_bnsh, p_rp_g, p_ei_g, batch, p_gsum, p_cnt);
    predict_kernel<<<NGRAPH, 256>>>(p_gsum, p_cnt, W_pred, b_pred, (float*)d_out);
}

// round 14
// speedup vs baseline: 1.5268x; 1.0159x over previous
#include <cuda_runtime.h>
#include <cuda_fp16.h>
#include <cstdint>

#define H 256
#define NGRAPH 128
#define MAXN   20224
#define MAXEG  200192
#define MAXELG 400128

// ---------------- scratch ----------------
__device__ float g_AB[(size_t)MAXN * 512];
__device__ float g_h[(size_t)MAXEG * H];
__device__ float g_nbg[(size_t)MAXEG * 4];
__device__ float g_ebg[(size_t)MAXELG * 4];
__device__ float g_bnacc[2 * H];
__device__ float g_bnscale[H];
__device__ float g_bnshift[H];
__device__ float g_gsum[NGRAPH * H];
__device__ float g_cnt[NGRAPH];

// CSR scratch
__device__ int g_deg[MAXEG];
__device__ int g_cursor[MAXEG];
__device__ int g_blk[1024];
__device__ int g_rowptr_lg[MAXEG + 1];
__device__ int g_eidx_lg[MAXELG];
__device__ int g_rowptr_g[MAXN + 1];
__device__ int g_eidx_g[MAXEG];

// fp16 activation buffers
__device__ __half g_node[(size_t)MAXN * H];
__device__ __half g_act[(size_t)MAXEG * H];
__device__ __half g_hid[(size_t)MAXEG * 2 * H];

// transposed/split fp16 weights arena
#define OFF_WMSG 0
#define OFF_W1T  (512 * 256)
#define OFF_W2T  (OFF_W1T + 4 * 131072)
#define WT_TOTAL (OFF_W2T + 4 * 131072)
__device__ __half g_wthi[WT_TOTAL];
__device__ __half g_wtlo[WT_TOTAL];

// ======================= helpers =======================
__device__ __forceinline__ uint32_t smem_u32(const void* p) {
    uint32_t a;
    asm("{ .reg .u64 t; cvta.to.shared.u64 t, %1; cvt.u32.u64 %0, t; }" : "=r"(a) : "l"(p));
    return a;
}
#define CP16(dst, src) \
    asm volatile("cp.async.cg.shared.global [%0], [%1], 16;" :: "r"(dst), "l"(src) : "memory")
#define CP16_CA(dst, src) \
    asm volatile("cp.async.ca.shared.global [%0], [%1], 16;" :: "r"(dst), "l"(src) : "memory")
#define CP_COMMIT() asm volatile("cp.async.commit_group;" ::: "memory")
#define CP_WAIT1()  asm volatile("cp.async.wait_group 1;" ::: "memory")
#define CP_WAIT0()  asm volatile("cp.async.wait_group 0;" ::: "memory")

__device__ __forceinline__ void ldm4(uint32_t (&r)[4], uint32_t addr) {
    asm volatile("ldmatrix.sync.aligned.m8n8.x4.shared.b16 {%0,%1,%2,%3}, [%4];"
                 : "=r"(r[0]), "=r"(r[1]), "=r"(r[2]), "=r"(r[3]) : "r"(addr));
}
__device__ __forceinline__ void mma_f16(float (&d)[4], const uint32_t (&a)[4], const uint32_t* b) {
    asm volatile(
        "mma.sync.aligned.m16n8k16.row.col.f32.f16.f16.f32 "
        "{%0,%1,%2,%3}, {%4,%5,%6,%7}, {%8,%9}, {%0,%1,%2,%3};"
        : "+f"(d[0]), "+f"(d[1]), "+f"(d[2]), "+f"(d[3])
        : "r"(a[0]), "r"(a[1]), "r"(a[2]), "r"(a[3]), "r"(b[0]), "r"(b[1]));
}

// ======================= CSR build kernels =======================
__global__ void zero_int_kernel(int* a, int n)
{
    int i = blockIdx.x * 256 + threadIdx.x;
    if (i < n) a[i] = 0;
}
__global__ void hist_kernel(const int* __restrict__ dst, int* __restrict__ deg, int E)
{
    int i = blockIdx.x * 256 + threadIdx.x;
    if (i < E) atomicAdd(&deg[dst[i]], 1);
}
__global__ void scan_block_sums(const int* __restrict__ deg, int* __restrict__ blk, int n)
{
    __shared__ int sd[256];
    int t = threadIdx.x;
    int i = blockIdx.x * 256 + t;
    sd[t] = (i < n) ? deg[i] : 0;
    __syncthreads();
    for (int o = 128; o > 0; o >>= 1) {
        if (t < o) sd[t] += sd[t + o];
        __syncthreads();
    }
    if (t == 0) blk[blockIdx.x] = sd[0];
}
__global__ void scan_single_block(int* blk, int nb)
{
    __shared__ int tmp[1024];
    int t = threadIdx.x;
    int v = (t < nb) ? blk[t] : 0;
    tmp[t] = v;
    __syncthreads();
    for (int o = 1; o < 1024; o <<= 1) {
        int u = (t >= o) ? tmp[t - o] : 0;
        __syncthreads();
        tmp[t] += u;
        __syncthreads();
    }
    if (t < nb) blk[t] = tmp[t] - v;
}
__global__ void scan_final(const int* __restrict__ deg, const int* __restrict__ blk,
                           int* __restrict__ rowptr, int* __restrict__ cursor, int n, int E)
{
    __shared__ int tmp[256];
    int t = threadIdx.x;
    int i = blockIdx.x * 256 + t;
    int v = (i < n) ? deg[i] : 0;
    tmp[t] = v;
    __syncthreads();
    for (int o = 1; o < 256; o <<= 1) {
        int u = (t >= o) ? tmp[t - o] : 0;
        __syncthreads();
        tmp[t] += u;
        __syncthreads();
    }
    int excl = tmp[t] - v + blk[blockIdx.x];
    if (i < n) { rowptr[i] = excl; cursor[i] = excl; }
    if (blockIdx.x == 0 && t == 0) rowptr[n] = E;
}
__global__ void fill_csr_kernel(const int* __restrict__ dst, int* __restrict__ cursor,
                                int* __restrict__ eidx, int E)
{
    int e = blockIdx.x * 256 + threadIdx.x;
    if (e < E) {
        int p = atomicAdd(&cursor[dst[e]], 1);
        eidx[p] = e;
    }
}

// ======================= mma.sync 2-term fp16 GEMM =======================
// flags: 1=bias, 2=relu, 4=residual fp32, 8=fp16 out, 32=BN stats (float bnacc[2N])
#define RB 80
#define TILE_B (128 * RB)
#define SO_A   0
#define SO_BHI (1 * TILE_B)
#define SO_BLO (2 * TILE_B)
#define STAGE_B (3 * TILE_B)
#define GEMM_SMEM (3 * STAGE_B)

__device__ __forceinline__ void load_stage(uint32_t sbase,
    const __half* __restrict__ A, const __half* __restrict__ B_hi,
    const __half* __restrict__ B_lo,
    int K, int m0, int n0, int k0, int tid)
{
#pragma unroll
    for (int i = 0; i < 2; i++) {
        int g = tid + i * 256;
        int row = g >> 2, ch = g & 3;
        uint32_t so = (uint32_t)row * RB + (uint32_t)ch * 16;
        size_t ao = (size_t)(m0 + row) * K + k0 + ch * 8;
        size_t bo = (size_t)(n0 + row) * K + k0 + ch * 8;
        CP16_CA(sbase + SO_A + so, A + ao);    // A shared by co-resident n-CTAs -> L1
        CP16(sbase + SO_BHI + so, B_hi + bo);
        CP16(sbase + SO_BLO + so, B_lo + bo);
    }
}

__global__ __launch_bounds__(256, 2) void mma_gemm_kernel(
    const __half* __restrict__ A,
    const __half* __restrict__ Bhi, const __half* __restrict__ Blo,
    const float* __restrict__ bias, const float* __restrict__ res,
    float* __restrict__ Cf, __half* __restrict__ Ch, float* __restrict__ bnacc,
    int M, int N, int K, int flags)
{
    extern __shared__ __align__(128) char smem[];
    uint32_t sb = smem_u32(smem);
    int tid = threadIdx.x;
    int wid = tid >> 5, lane = tid & 31;
    int m0 = blockIdx.y * 128, n0 = blockIdx.x * 128;
    int nk = K >> 5;

    load_stage(sb, A, Bhi, Blo, K, m0, n0, 0, tid);
    CP_COMMIT();
    load_stage(sb + STAGE_B, A, Bhi, Blo, K, m0, n0, 32, tid);
    CP_COMMIT();

    float acc[4][4][4];
#pragma unroll
    for (int i = 0; i < 4; i++)
#pragma unroll
        for (int j = 0; j < 4; j++)
#pragma unroll
            for (int q = 0; q < 4; q++) acc[i][j][q] = 0.f;

    int mo = (wid & 1) * 64, no = (wid >> 1) * 32;
    int a_row = mo + (lane & 15);
    int a_k8  = lane >> 4;
    int b_row = ((lane >> 4) << 3) + (lane & 7);
    int b_k8  = (lane >> 3) & 1;

    for (int k = 0; k < nk; k++) {
        if (k == nk - 1) { CP_WAIT0(); } else { CP_WAIT1(); }
        __syncthreads();
        uint32_t base = sb + (uint32_t)(k % 3) * STAGE_B;
        if (k + 2 < nk)
            load_stage(sb + (uint32_t)((k + 2) % 3) * STAGE_B, A, Bhi, Blo,
                       K, m0, n0, (k + 2) * 32, tid);
        CP_COMMIT();
#pragma unroll
        for (int k16 = 0; k16 < 2; k16++) {
            int kk8 = k16 * 2;
            uint32_t ah[4][4], bh[2][4], bl[2][4];
#pragma unroll
            for (int i = 0; i < 4; i++) {
                uint32_t aaddr = base + SO_A + (uint32_t)(a_row + i * 16) * RB
                               + (uint32_t)(kk8 + a_k8) * 16;
                ldm4(ah[i], aaddr);
            }
#pragma unroll
            for (int j = 0; j < 2; j++) {
                uint32_t baddr = base + SO_BHI + (uint32_t)(no + j * 16 + b_row) * RB
                               + (uint32_t)(kk8 + b_k8) * 16;
                ldm4(bh[j], baddr);
                ldm4(bl[j], baddr + (SO_BLO - SO_BHI));
            }
#pragma unroll
            for (int j = 0; j < 2; j++)
#pragma unroll
                for (int i = 0; i < 4; i++) {
                    mma_f16(acc[i][2 * j],     ah[i], &bh[j][0]);
                    mma_f16(acc[i][2 * j + 1], ah[i], &bh[j][2]);
                }
#pragma unroll
            for (int j = 0; j < 2; j++)
#pragma unroll
                for (int i = 0; i < 4; i++) {
                    mma_f16(acc[i][2 * j],     ah[i], &bl[j][0]);
                    mma_f16(acc[i][2 * j + 1], ah[i], &bl[j][2]);
                }
        }
    }

    // epilogue (+ optional fused BN statistics)
    float st[4][2], sq[4][2];
#pragma unroll
    for (int nb = 0; nb < 4; nb++) {
        st[nb][0] = st[nb][1] = 0.f;
        sq[nb][0] = sq[nb][1] = 0.f;
    }
#pragma unroll
    for (int i = 0; i < 4; i++) {
        int r0 = m0 + mo + i * 16 + (lane >> 2);
#pragma unroll
        for (int half = 0; half < 2; half++) {
            int r = r0 + half * 8;
            if (r >= M) continue;
#pragma unroll
            for (int nb = 0; nb < 4; nb++) {
                int col = n0 + no + nb * 8 + 2 * (lane & 3);
                float v0 = acc[i][nb][half * 2 + 0];
                float v1 = acc[i][nb][half * 2 + 1];
                if (flags & 1) { v0 += bias[col]; v1 += bias[col + 1]; }
                if (flags & 4) {
                    float2 t = *(const float2*)(res + (size_t)r * N + col);
                    v0 += t.x; v1 += t.y;
                }
                if (flags & 2) { v0 = fmaxf(v0, 0.f); v1 = fmaxf(v1, 0.f); }
                if (flags & 32) {
                    st[nb][0] += v0; sq[nb][0] = fmaf(v0, v0, sq[nb][0]);
                    st[nb][1] += v1; sq[nb][1] = fmaf(v1, v1, sq[nb][1]);
                }
                if (flags & 8) {
                    *(__half2*)(Ch + (size_t)r * N + col) =
                        __halves2half2(__float2half(v0), __float2half(v1));
                } else {
                    *(float2*)(Cf + (size_t)r * N + col) = make_float2(v0, v1);
                }
            }
        }
    }
    if (flags & 32) {
#pragma unroll
        for (int nb = 0; nb < 4; nb++)
#pragma unroll
            for (int w = 0; w < 2; w++) {
                float s = st[nb][w], q = sq[nb][w];
                s += __shfl_xor_sync(0xffffffffu, s, 4);
                q += __shfl_xor_sync(0xffffffffu, q, 4);
                s += __shfl_xor_sync(0xffffffffu, s, 8);
                q += __shfl_xor_sync(0xffffffffu, q, 8);
                s += __shfl_xor_sync(0xffffffffu, s, 16);
                q += __shfl_xor_sync(0xffffffffu, q, 16);
                if ((lane >> 2) == 0) {
                    int col = n0 + no + nb * 8 + 2 * (lane & 3) + w;
                    atomicAdd(&bnacc[col], s);
                    atomicAdd(&bnacc[N + col], q);
                }
            }
    }
}

// ---------------- ALL weight transpose+splits in one kernel --------------------
__global__ void tsplit_all_kernel(const float* __restrict__ Wmsg,
                                  const float* __restrict__ W1,
                                  const float* __restrict__ W2,
                                  __half* __restrict__ thi, __half* __restrict__ tlo)
{
    int idx = blockIdx.x * 256 + threadIdx.x;
    if (idx >= 1179648) return;
    float w;
    size_t dofs;
    if (idx < 131072) {                       // msg: two 256x256 halves
        int part = idx >> 16, e = idx & 65535;
        int k = e >> 8, n = e & 255;
        w = Wmsg[(size_t)part * 65536 + (size_t)k * 256 + n];
        dofs = (size_t)OFF_WMSG + part * 65536 + (size_t)n * 256 + k;
    } else if (idx < 655360) {                // W1: 4 layers, K=256 N=512
        int e = idx - 131072;
        int l = e >> 17, el = e & 131071;
        int k = el >> 9, n = el & 511;
        w = W1[(size_t)l * 131072 + (size_t)k * 512 + n];
        dofs = (size_t)OFF_W1T + (size_t)l * 131072 + (size_t)n * 256 + k;
    } else {                                  // W2: 4 layers, K=512 N=256
        int e = idx - 655360;
        int l = e >> 17, el = e & 131071;
        int k = el >> 8, n = el & 255;
        w = W2[(size_t)l * 131072 + (size_t)k * 256 + n];
        dofs = (size_t)OFF_W2T + (size_t)l * 131072 + (size_t)n * 512 + k;
    }
    __half hi = __float2half(w);
    __half lo = __float2half(w - __half2float(hi));
    thi[dofs] = hi;
    tlo[dofs] = lo;
}

// ---------------- node encoder (fp16 out) --------------------------------------
__global__ void enc_kernel(const float* __restrict__ xg, const float* __restrict__ W,
                           const float* __restrict__ b, __half* __restrict__ out)
{
    __shared__ float sx[16];
    int n = blockIdx.x, c = threadIdx.x;
    if (c < 16) sx[c] = xg[(size_t)n * 16 + c];
    __syncthreads();
    float v = b[c];
#pragma unroll
    for (int k = 0; k < 16; k++) v = fmaf(sx[k], W[k * H + c], v);
    out[(size_t)n * H + c] = __float2half(v);
}

// ---------------- combined tiny [.,4]@[4,4]+b projections ----------------------
__global__ void basis4_both_kernel(const float* __restrict__ in1, const float* __restrict__ W1,
                                   const float* __restrict__ b1v, float* __restrict__ out1, int E1,
                                   const float* __restrict__ in2, const float* __restrict__ W2,
                                   const float* __restrict__ b2v, float* __restrict__ out2, int E2)
{
    int e = blockIdx.x * blockDim.x + threadIdx.x;
    const float* in; const float* W; const float* b; float* out;
    if (e < E1) { in = in1; W = W1; b = b1v; out = out1; }
    else { e -= E1; if (e >= E2) return; in = in2; W = W2; b = b2v; out = out2; }
    float4 x = *(const float4*)(in + (size_t)e * 4);
    float o0 = b[0] + x.x * W[0] + x.y * W[4] + x.z * W[8]  + x.w * W[12];
    float o1 = b[1] + x.x * W[1] + x.y * W[5] + x.z * W[9]  + x.w * W[13];
    float o2 = b[2] + x.x * W[2] + x.y * W[6] + x.z * W[10] + x.w * W[14];
    float o3 = b[3] + x.x * W[3] + x.y * W[7] + x.z * W[11] + x.w * W[15];
    *(float4*)(out + (size_t)e * 4) = make_float4(o0, o1, o2, o3);
}

// ---------------- fused first-message ------------------------------------------
#define MEPB 16
__global__ __launch_bounds__(256) void msg_edge_kernel(
    const float* __restrict__ AB,
    const float* __restrict__ ea, const float* __restrict__ xlg,
    const float* __restrict__ Wc, const float* __restrict__ Wd,
    const float* __restrict__ bmsg,
    const int* __restrict__ srcg, const int* __restrict__ dstg,
    float* __restrict__ h, int Eg)
{
    __shared__ float sWc[16 * H];
    __shared__ float sWd[4 * H];
    __shared__ float sb[H];
    __shared__ float sea[MEPB][16];
    __shared__ float sxl[MEPB][4];
    int tid = threadIdx.x;
    for (int i = tid; i < 16 * H; i += 256) sWc[i] = Wc[i];
    for (int i = tid; i < 4 * H; i += 256) sWd[i] = Wd[i];
    sb[tid] = bmsg[tid];
    int e0 = blockIdx.x * MEPB;
    for (int i = tid; i < MEPB * 16; i += 256) {
        int e = e0 + i / 16;
        if (e < Eg) sea[i / 16][i % 16] = ea[(size_t)e * 16 + (i % 16)];
    }
    for (int i = tid; i < MEPB * 4; i += 256) {
        int e = e0 + i / 4;
        if (e < Eg) sxl[i / 4][i % 4] = xlg[(size_t)e * 4 + (i % 4)];
    }
    __syncthreads();
    int c = tid;
    for (int i = 0; i < MEPB; i++) {
        int e = e0 + i;
        if (e >= Eg) break;
        int s = srcg[e], d = dstg[e];
        float v = AB[(size_t)s * 512 + c] + AB[(size_t)d * 512 + 256 + c] + sb[c];
#pragma unroll
        for (int k = 0; k < 16; k++) v = fmaf(sea[i][k], sWc[k * H + c], v);
#pragma unroll
        for (int k = 0; k < 4; k++) v = fmaf(sxl[i][k], sWd[k * H + c], v);
        h[(size_t)e * H + c] = v;
    }
}

// ---------------- BN coefficient computation (reads then self-zeroes acc) ------
__global__ void bn_coef_kernel(float* __restrict__ acc,
                               const float* __restrict__ gamma, const float* __restrict__ beta,
                               float* __restrict__ scale, float* __restrict__ shift, int M)
{
    int c = threadIdx.x;
    float a0 = acc[c], a1 = acc[H + c];
    acc[c] = 0.f;
    acc[H + c] = 0.f;
    double mu = (double)a0 / (double)M;
    double var = (double)a1 / (double)M - mu * mu;
    float inv = rsqrtf((float)var + 1e-5f);
    float sc = gamma[c] * inv;
    scale[c] = sc;
    shift[c] = beta[c] - (float)mu * sc;
}

// ---------------- fused GENConv aggregation (CSR gather, fp16 out) -------------
#define RPB 8
__global__ __launch_bounds__(256) void gen_aggr_kernel(
    const float* __restrict__ x, const float* __restrict__ nbg, const float* __restrict__ ebg,
    const float* __restrict__ Wnb, const float* __restrict__ bnb,
    const float* __restrict__ Web, const float* __restrict__ beb,
    const float* __restrict__ bnscale, const float* __restrict__ bnshift,
    const int* __restrict__ src, const int* __restrict__ rowptr, const int* __restrict__ eidx,
    __half* __restrict__ aout, int E, int use_bn)
{
    __shared__ float sWn[4 * H], sWe[4 * H], sbn[H], sbe[H];
    int tid = threadIdx.x;
    for (int i = tid; i < 4 * H; i += 256) { sWn[i] = Wnb[i]; sWe[i] = Web[i]; }
    sbn[tid] = bnb[tid];
    sbe[tid] = beb[tid];
    __syncthreads();
    int c = tid;
    float sc = 1.f, sh = 0.f;
    if (use_bn) { sc = bnscale[c]; sh = bnshift[c]; }
    int d0 = blockIdx.x * RPB;
#pragma unroll
    for (int rr = 0; rr < RPB; rr++) {
        int d = d0 + rr;
        if (d >= E) break;
        int beg = rowptr[d], end = rowptr[d + 1];
        float se = 0.f, sw = 0.f, m0 = 0.f;
        for (int p = beg; p < end; p++) {
            int e = eidx[p];
            int s = src[e];
            float4 nv = *(const float4*)(nbg + (size_t)s * 4);
            float4 ev4 = *(const float4*)(ebg + (size_t)e * 4);
            float nbv = sbn[c];
            nbv = fmaf(nv.x, sWn[c], nbv);
            nbv = fmaf(nv.y, sWn[H + c], nbv);
            nbv = fmaf(nv.z, sWn[2 * H + c], nbv);
            nbv = fmaf(nv.w, sWn[3 * H + c], nbv);
            float ebv = sbe[c];
            ebv = fmaf(ev4.x, sWe[c], ebv);
            ebv = fmaf(ev4.y, sWe[H + c], ebv);
            ebv = fmaf(ev4.z, sWe[2 * H + c], ebv);
            ebv = fmaf(ev4.w, sWe[3 * H + c], ebv);
            float xv = x[(size_t)s * H + c];
            if (use_bn) xv = fmaxf(fmaf(xv, sc, sh), 0.f);
            float mv = fmaxf(xv + nbv + ebv, 0.f) + 1e-7f;
            if (p == beg) {
                m0 = mv;
                se = 1.f;
                sw = mv;
            } else {
                float dmv = fminf(fmaxf(mv - m0, -80.f), 80.f);
                float ee = __expf(dmv);
                se += ee;
                sw = fmaf(ee, mv, sw);
            }
        }
        float xv = x[(size_t)d * H + c];
        if (use_bn) xv = fmaxf(fmaf(xv, sc, sh), 0.f);
        float v = xv + __fdividef(sw, se + 1e-16f);
        aout[(size_t)d * H + c] = __float2half(v);
    }
}

// ---------------- fused node gather + graph pool (BN fused) --------------------
__global__ void node_pool_kernel(const float* __restrict__ h,
                                 const float* __restrict__ bnscale,
                                 const float* __restrict__ bnshift,
                                 const int* __restrict__ rowptr, const int* __restrict__ eidx,
                                 const int* __restrict__ batch,
                                 float* __restrict__ gsum, float* __restrict__ cnt)
{
    int n = blockIdx.x, c = threadIdx.x;
    float sc = bnscale[c], sh = bnshift[c];
    int beg = rowptr[n], end = rowptr[n + 1];
    float acc = 0.f;
    for (int p = beg; p < end; p++) {
        int e = eidx[p];
        acc += fmaf(h[(size_t)e * H + c], sc, sh);
    }
    int b = batch[n];
    atomicAdd(gsum + (size_t)b * H + c, acc);
    if (c == 0) atomicAdd(&cnt[b], 1.0f);
}

__global__ void predict_kernel(const float* __restrict__ gsum, const float* __restrict__ cnt,
                               const float* __restrict__ Wp, const float* __restrict__ bp,
                               float* __restrict__ out)
{
    int g = blockIdx.x, c = threadIdx.x;
    float v = gsum[(size_t)g * H + c] * Wp[c];
    __shared__ float red[8];
#pragma unroll
    for (int o = 16; o > 0; o >>= 1) v += __shfl_down_sync(0xffffffffu, v, o);
    if ((c & 31) == 0) red[c >> 5] = v;
    __syncthreads();
    if (c == 0) {
        float t = 0.f;
#pragma unroll
        for (int i = 0; i < 8; i++) t += red[i];
        out[g] = t / fmaxf(cnt[g], 1.0f) + bp[0];
    }
}

// -------------------------------------------------------------------------------
static void* symA(const void* sym)
{
    void* p = nullptr;
    cudaGetSymbolAddress(&p, sym);
    return p;
}

static void build_csr(const int* dst, int n, int E, int* deg, int* blk,
                      int* rowptr, int* cursor, int* eidx)
{
    int nb = (n + 255) / 256;
    zero_int_kernel<<<nb, 256>>>(deg, n);
    hist_kernel<<<(E + 255) / 256, 256>>>(dst, deg, E);
    scan_block_sums<<<nb, 256>>>(deg, blk, n);
    scan_single_block<<<1, 1024>>>(blk, nb);
    scan_final<<<nb, 256>>>(deg, blk, rowptr, cursor, n, E);
    fill_csr_kernel<<<(E + 255) / 256, 256>>>(dst, cursor, eidx, E);
}

extern "C" void kernel_launch(void* const* d_in, const int* in_sizes, int n_in,
                              void* d_out, int out_size)
{
    const float* x_g       = (const float*)d_in[0];
    const float* ea_g      = (const float*)d_in[1];
    const float* x_lg      = (const float*)d_in[2];
    const float* edb       = (const float*)d_in[3];
    const float* ea_lg     = (const float*)d_in[4];
    const float* W_enc     = (const float*)d_in[5];
    const float* b_enc     = (const float*)d_in[6];
    const float* W_msg     = (const float*)d_in[7];
    const float* b_msg     = (const float*)d_in[8];
    const float* Wg_nb     = (const float*)d_in[9];
    const float* bg_nb     = (const float*)d_in[10];
    const float* Wg_eb     = (const float*)d_in[11];
    const float* bg_eb     = (const float*)d_in[12];
    const float* Wl_nb     = (const float*)d_in[13];
    const float* bl_nb     = (const float*)d_in[14];
    const float* Wl_eb     = (const float*)d_in[15];
    const float* bl_eb     = (const float*)d_in[16];
    const float* W1        = (const float*)d_in[17];
    const float* b1        = (const float*)d_in[18];
    const float* W2        = (const float*)d_in[19];
    const float* b2        = (const float*)d_in[20];
    const float* bn_gamma  = (const float*)d_in[21];
    const float* bn_beta   = (const float*)d_in[22];
    const float* W_pred    = (const float*)d_in[23];
    const float* b_pred    = (const float*)d_in[24];
    const int*   eig       = (const int*)d_in[25];
    const int*   eil       = (const int*)d_in[26];
    const int*   batch     = (const int*)d_in[27];

    int N   = in_sizes[0] / 16;   // 20000
    int Eg  = in_sizes[1] / 16;   // 200000
    int Elg = in_sizes[4] / 4;    // 400000
    const int L = 4;

    cudaFuncSetAttribute(mma_gemm_kernel, cudaFuncAttributeMaxDynamicSharedMemorySize,
                         GEMM_SMEM);

    float* p_AB   = (float*)symA(g_AB);
    float* p_h    = (float*)symA(g_h);
    float* p_nbg  = (float*)symA(g_nbg);
    float* p_ebg  = (float*)symA(g_ebg);
    float* p_bnacc = (float*)symA(g_bnacc);
    float* p_bnsc = (float*)symA(g_bnscale);
    float* p_bnsh = (float*)symA(g_bnshift);
    float* p_gsum = (float*)symA(g_gsum);
    float* p_cnt  = (float*)symA(g_cnt);

    int* p_deg    = (int*)symA(g_deg);
    int* p_cursor = (int*)symA(g_cursor);
    int* p_blk    = (int*)symA(g_blk);
    int* p_rp_lg  = (int*)symA(g_rowptr_lg);
    int* p_ei_lg  = (int*)symA(g_eidx_lg);
    int* p_rp_g   = (int*)symA(g_rowptr_g);
    int* p_ei_g   = (int*)symA(g_eidx_g);

    __half* p_node = (__half*)symA(g_node);
    __half* p_act  = (__half*)symA(g_act);
    __half* p_hid  = (__half*)symA(g_hid);
    __half* p_wthi = (__half*)symA(g_wthi);
    __half* p_wtlo = (__half*)symA(g_wtlo);

    const int* src_g = eig;
    const int* dst_g = eig + Eg;
    const int* src_l = eil;
    const int* dst_l = eil + Elg;

    int mtE = (Eg + 127) / 128;   // 1563
    int mtN = (N + 127) / 128;    // 157

    // --- launch order front-loads mma_gemm into capture slots 3..6 ---
    // 1: all weight transpose+splits in one kernel
    tsplit_all_kernel<<<(1179648 + 255) / 256, 256>>>(W_msg, W1, W2, p_wthi, p_wtlo);
    // 2: node encoder
    enc_kernel<<<N, 256>>>(x_g, W_enc, b_enc, p_node);
    // 3..6: msg GEMM as four n-tile launches (diagnostic positioning)
    for (int t = 0; t < 4; t++) {
        dim3 grid(1, mtN);
        mma_gemm_kernel<<<grid, 256, GEMM_SMEM>>>(
            p_node,
            p_wthi + OFF_WMSG + (size_t)t * 128 * 256,
            p_wtlo + OFF_WMSG + (size_t)t * 128 * 256,
            nullptr, nullptr, p_AB + t * 128, nullptr, nullptr, N, 512, 256, 0);
    }
    // 7+: basis, msg_edge, CSR builds
    basis4_both_kernel<<<(Eg + Elg + 255) / 256, 256>>>(
        edb, Wg_nb, bg_nb, p_nbg, Eg,
        ea_lg, Wg_eb, bg_eb, p_ebg, Elg);
    msg_edge_kernel<<<(Eg + MEPB - 1) / MEPB, 256>>>(
        p_AB, ea_g, x_lg, W_msg + 512 * H, W_msg + 528 * H, b_msg,
        src_g, dst_g, p_h, Eg);
    build_csr(dst_l, Eg, Elg, p_deg, p_blk, p_rp_lg, p_cursor, p_ei_lg);
    build_csr(dst_g, N, Eg, p_deg, p_blk, p_rp_g, p_cursor, p_ei_g);

    // safety: ensure bnacc zero before layer-0 GEMM2 (bn_coef self-zeroes after)
    cudaMemsetAsync(p_bnacc, 0, 2 * H * sizeof(float));

    // --- 4 GENConv layers ---
    for (int l = 0; l < L; l++) {
        int use_bn = (l > 0) ? 1 : 0;
        if (use_bn) {
            bn_coef_kernel<<<1, 256>>>(p_bnacc, bn_gamma + (l - 1) * H, bn_beta + (l - 1) * H,
                                       p_bnsc, p_bnsh, Eg);
        }
        gen_aggr_kernel<<<(Eg + RPB - 1) / RPB, 256>>>(
            p_h, p_nbg, p_ebg,
            Wl_nb + l * 4 * H, bl_nb + l * H,
            Wl_eb + l * 4 * H, bl_eb + l * H,
            p_bnsc, p_bnsh, src_l, p_rp_lg, p_ei_lg,
            p_act, Eg, use_bn);

        // GEMM1: hid = relu(act @ W1 + b1), fp16 out
        {
            dim3 grid(4, mtE);
            mma_gemm_kernel<<<grid, 256, GEMM_SMEM>>>(
                p_act, p_wthi + OFF_W1T + l * 131072, p_wtlo + OFF_W1T + l * 131072,
                b1 + l * 512, nullptr, nullptr, p_hid, nullptr,
                Eg, 512, 256, 1 | 2 | 8);
        }
        // GEMM2: h = hid @ W2 + b2 (+ residual for l>0), fp32 out + fused BN stats
        {
            dim3 grid(2, mtE);
            mma_gemm_kernel<<<grid, 256, GEMM_SMEM>>>(
                p_hid, p_wthi + OFF_W2T + l * 131072, p_wtlo + OFF_W2T + l * 131072,
                b2 + l * 256, (l > 0) ? p_h : nullptr, p_h, nullptr, p_bnacc,
                Eg, 256, 512, ((l > 0) ? (1 | 4) : 1) | 32);
        }
    }

    // --- final BN coefs + fused node gather/pool ---
    bn_coef_kernel<<<1, 256>>>(p_bnacc, bn_gamma + 3 * H, bn_beta + 3 * H, p_bnsc, p_bnsh, Eg);

    cudaMemsetAsync(p_gsum, 0, NGRAPH * H * sizeof(float));
    cudaMemsetAsync(p_cnt,  0, NGRAPH * sizeof(float));
    node_pool_kernel<<<N, 256>>>(p_h, p_bnsc, p_bnsh, p_rp_g, p_ei_g, batch, p_gsum, p_cnt);
    predict_kernel<<<NGRAPH, 256>>>(p_gsum, p_cnt, W_pred, b_pred, (float*)d_out);
}